// round 10
// baseline (speedup 1.0000x reference)
#include <cuda_runtime.h>
#include <cuda_fp16.h>
#include <cstdint>
#include <cstddef>

#define HH 512
#define WW 512
#define BB 8
constexpr int HW = HH * WW;
constexpr size_t SST = (size_t)BB * HW * 4;   // floats per head-stage buffer

// ---------------- scratch ----------------
__device__ float g_B1[(size_t)BB * HW * 32 / 2];   // fp16 NHWC 32ch (natural order)
__device__ float g_B2[(size_t)BB * HW * 64];       // fp16 64ch / 3x packed HP stage buffers
__device__ float g_P[BB * 16 * 12];
__device__ float g_S[3 * BB * 4];
__device__ float g_TX[(size_t)BB * 3 * HW];
__device__ float g_TX2[(size_t)BB * 3 * HW];
__device__ uint2 g_W2[9 * 2 * 64 * 4];
__device__ uint2 g_W3[9 * 4 * 32 * 4];
__device__ uint2 g_WH[9 * 2 * 16 * 4];

// ---------------- helpers ----------------
__device__ __forceinline__ uint32_t smem_u32(const void* p) {
    uint32_t r;
    asm("{ .reg .u64 t; cvta.to.shared.u64 t, %1; cvt.u32.u64 %0, t; }" : "=r"(r) : "l"(p));
    return r;
}
__device__ __forceinline__ uint32_t pack_h2(float a, float b) {
    __half2 h = __floats2half2_rn(a, b);
    return *(uint32_t*)&h;
}
__device__ __forceinline__ void mma16(float* d, uint32_t a0, uint32_t a1, uint32_t a2,
                                      uint32_t a3, uint32_t b0, uint32_t b1) {
    asm volatile(
        "mma.sync.aligned.m16n8k16.row.col.f32.f16.f16.f32 "
        "{%0,%1,%2,%3}, {%4,%5,%6,%7}, {%8,%9}, {%0,%1,%2,%3};"
        : "+f"(d[0]), "+f"(d[1]), "+f"(d[2]), "+f"(d[3])
        : "r"(a0), "r"(a1), "r"(a2), "r"(a3), "r"(b0), "r"(b1));
}
__device__ __forceinline__ void ldsm4(uint32_t* r, uint32_t addr) {
    asm volatile("ldmatrix.sync.aligned.m8n8.x4.shared.b16 {%0,%1,%2,%3}, [%4];"
                 : "=r"(r[0]), "=r"(r[1]), "=r"(r[2]), "=r"(r[3]) : "r"(addr));
}
__device__ __forceinline__ void fma2(unsigned long long& d, unsigned long long a,
                                     unsigned long long b) {
    asm("fma.rn.f32x2 %0, %1, %2, %0;" : "+l"(d) : "l"(a), "l"(b));
}
#define CP_A16(dst, src) asm volatile("cp.async.ca.shared.global [%0], [%1], 16;" :: "r"(dst), "l"(src) : "memory")
#define CP_COMMIT()      asm volatile("cp.async.commit_group;" ::: "memory")
#define CP_WAIT0()       asm volatile("cp.async.wait_group 0;" ::: "memory")
#define STZ16(dst)       asm volatile("st.shared.v4.b32 [%0], {%1,%1,%1,%1};" :: "r"(dst), "r"(0u) : "memory")

// ================= fused weight pre-transform =================
__device__ void wprep_one(const float* wA, const float* wB2, const float* wC,
                          int CIN, int NTOT, int H3, uint2* out, int i)
{
    const int NKS = CIN / 16;
    const int tap = i / (NKS * NTOT * 4);
    int r = i % (NKS * NTOT * 4);
    const int ks = r / (NTOT * 4);
    r %= NTOT * 4;
    const int n = r >> 2, t4 = r & 3;
    float v0 = 0.f, v1 = 0.f, v2 = 0.f, v3 = 0.f;
    const int cb = ks * 16 + t4 * 2;
    if (H3) {
        if (n < 12) {
            const float* wp = (n < 4) ? wA : (n < 8 ? wB2 : wC);
            const size_t nb = (size_t)(n & 3) * CIN;
            v0 = wp[(nb + cb) * 9 + tap];
            v1 = wp[(nb + cb + 1) * 9 + tap];
            v2 = wp[(nb + cb + 8) * 9 + tap];
            v3 = wp[(nb + cb + 9) * 9 + tap];
        }
    } else {
        const size_t nb = (size_t)n * CIN;
        v0 = wA[(nb + cb) * 9 + tap];
        v1 = wA[(nb + cb + 1) * 9 + tap];
        v2 = wA[(nb + cb + 8) * 9 + tap];
        v3 = wA[(nb + cb + 9) * 9 + tap];
    }
    uint2 e;
    e.x = pack_h2(v0, v1);
    e.y = pack_h2(v2, v3);
    out[i] = e;
}

__global__ void wprep_k(const float* __restrict__ w2, const float* __restrict__ w3,
                        const float* __restrict__ hA, const float* __restrict__ hB,
                        const float* __restrict__ hC,
                        uint2* __restrict__ o2, uint2* __restrict__ o3, uint2* __restrict__ oH)
{
    constexpr int T2 = 9 * 2 * 64 * 4;
    constexpr int T3 = 9 * 4 * 32 * 4;
    constexpr int TH = 9 * 2 * 16 * 4;
    int i = blockIdx.x * 256 + threadIdx.x;
    if (i < T2) { wprep_one(w2, nullptr, nullptr, 32, 64, 0, o2, i); return; }
    i -= T2;
    if (i < T3) { wprep_one(w3, nullptr, nullptr, 64, 32, 0, o3, i); return; }
    i -= T3;
    if (i < TH) { wprep_one(hA, hB, hC, 32, 16, 1, oH, i); }
}

// ================= fp16 m16n8k16 3x3 conv (ldmatrix A fragments) =================
template<int CIN, int NTOT, int MW, int MT, int NT, bool H3>
__global__ __launch_bounds__(256) void mconv_k(
    const __half* __restrict__ in, const uint2* __restrict__ wp,
    const float* __restrict__ bA, const float* __restrict__ bB2, const float* __restrict__ bC,
    const float* __restrict__ pr, void* __restrict__ outv)
{
    constexpr int P = MW * MT * 16;
    constexpr int PP = P + 2;
    constexpr int NKS = CIN / 16;
    constexpr int SEGS = 2 * NKS;
    constexpr int SLOTU2 = NKS * PP * 4;
    constexpr int WSEGS = 9 * NKS * NTOT * 2;

    extern __shared__ __align__(16) char smraw[];
    const uint2* w_u2 = (const uint2*)smraw + 4 * SLOTU2;
    const uint32_t a_u = smem_u32(smraw);
    const uint32_t w_addr = a_u + (uint32_t)(4 * SLOTU2 * 8);

    const int tid = threadIdx.x;
    const int lane = tid & 31;
    const int wid = tid >> 5;
    const int g = lane >> 2, tg = lane & 3;
    const int lrow = lane & 15, lhalf = lane >> 4;
    const int mbase = (wid % MW) * MT * 16;
    const int nbase = (wid / MW) * NT * 8;
    const int x0 = blockIdx.x * P;
    const int y0 = blockIdx.y * 8;
    const int b = blockIdx.z;

    const __half* inb = in + (size_t)b * HW * CIN;

    auto stage = [&](int yy) {
        const int slot = (yy + 4) & 3;
        const uint32_t sbase = a_u + (uint32_t)(slot * SLOTU2 * 8);
        const bool rok = ((unsigned)yy < HH);
        const __half* rowp = inb + (size_t)yy * WW * CIN;
        for (int i = tid; i < PP * SEGS; i += 256) {
            const int p = i / SEGS;
            const int s = i % SEGS;
            const int ks = s >> 1, h = s & 1;
            const int gx = x0 + p - 1;
            const uint32_t dst = sbase + (uint32_t)(((ks * PP + p) * 32) + h * 16);
            if (rok && (unsigned)gx < WW)
                CP_A16(dst, rowp + (size_t)gx * CIN + ks * 16 + h * 8);
            else
                STZ16(dst);
        }
    };

    for (int i = tid; i < WSEGS; i += 256)
        CP_A16(w_addr + (uint32_t)i * 16, (const char*)wp + (size_t)i * 16);
    stage(y0 - 1); stage(y0); stage(y0 + 1);
    CP_COMMIT();

    __half* obH = (__half*)outv + (size_t)b * HW * NTOT;
    const float alpha = pr ? pr[0] : 0.f;

    // per-lane base offset for ldmatrix addressing (within a K-group row block)
    const uint32_t lmoff = (uint32_t)((mbase + lrow) * 32 + lhalf * 16);

    #pragma unroll 1
    for (int yi = 0; yi < 8; yi++) {
        const int y = y0 + yi;
        CP_WAIT0();
        __syncthreads();
        if (yi < 7) { stage(y + 2); CP_COMMIT(); }

        float acc[MT][NT][4];
        #pragma unroll
        for (int mt = 0; mt < MT; mt++)
            #pragma unroll
            for (int nt = 0; nt < NT; nt++)
                #pragma unroll
                for (int e = 0; e < 4; e++) acc[mt][nt][e] = 0.f;

        #pragma unroll 1
        for (int tap = 0; tap < 9; tap++) {
            const int dy = tap / 3, dx = tap - dy * 3;
            const int slot = (y + dy + 3) & 3;
            #pragma unroll
            for (int ks = 0; ks < NKS; ks++) {
                const uint32_t abase = a_u + (uint32_t)((slot * NKS + ks) * PP * 32 + dx * 32) + lmoff;
                uint32_t m[MT][4];
                #pragma unroll
                for (int mt = 0; mt < MT; mt++)
                    ldsm4(m[mt], abase + (uint32_t)(mt * 16 * 32));
                #pragma unroll
                for (int nt = 0; nt < NT; nt++) {
                    const uint2 qw = w_u2[((tap * NKS + ks) * NTOT + nbase + nt * 8 + g) * 4 + tg];
                    #pragma unroll
                    for (int mt = 0; mt < MT; mt++)
                        mma16(acc[mt][nt], m[mt][0], m[mt][1], m[mt][2], m[mt][3], qw.x, qw.y);
                }
            }
        }

        // ---- epilogue (natural NHWC) ----
        #pragma unroll
        for (int mt = 0; mt < MT; mt++) {
            const int px = x0 + mbase + mt * 16 + g;
            #pragma unroll
            for (int nt = 0; nt < NT; nt++) {
                const int ch = nbase + nt * 8 + tg * 2;   // even
                if (H3) {
                    if (ch < 12) {
                        const int st = ch >> 2, c4 = ch & 3;
                        const float* bp = (st == 0) ? bA : (st == 1 ? bB2 : bC);
                        const float bv0 = bp[c4], bv1 = bp[c4 + 1];
                        float* hb = (float*)outv + st * SST + (size_t)b * HW * 4;
                        float2 lo = make_float2(acc[mt][nt][0] + bv0, acc[mt][nt][1] + bv1);
                        float2 hi = make_float2(acc[mt][nt][2] + bv0, acc[mt][nt][3] + bv1);
                        *(float2*)(hb + ((size_t)y * WW + px) * 4 + c4) = lo;
                        *(float2*)(hb + ((size_t)y * WW + px + 8) * 4 + c4) = hi;
                    }
                } else {
                    const float bv0 = bA[ch], bv1 = bA[ch + 1];
                    float v0 = acc[mt][nt][0] + bv0;
                    float v1 = acc[mt][nt][1] + bv1;
                    float v2 = acc[mt][nt][2] + bv0;
                    float v3 = acc[mt][nt][3] + bv1;
                    if (v0 < 0.f) v0 *= alpha;
                    if (v1 < 0.f) v1 *= alpha;
                    if (v2 < 0.f) v2 *= alpha;
                    if (v3 < 0.f) v3 *= alpha;
                    *(uint32_t*)(obH + ((size_t)y * WW + px) * NTOT + ch) = pack_h2(v0, v1);
                    *(uint32_t*)(obH + ((size_t)y * WW + px + 8) * NTOT + ch) = pack_h2(v2, v3);
                }
            }
        }
    }
}

// ================= conv1: 3->32, f32x2 FMA + LDS.128 weights, natural NHWC out =================
__global__ __launch_bounds__(256) void conv1_k(
    const float* __restrict__ x, const float* __restrict__ w,
    const float* __restrict__ bias, const float* __restrict__ pr,
    __half* __restrict__ out)
{
    __shared__ float s_in[3][10][34];
    __shared__ ulonglong2 s_w4[27][8];
    __shared__ float s_b[32];

    const int tid = threadIdx.x;
    const int tx = tid & 31, ty = tid >> 5;
    const int x0 = blockIdx.x * 32, y0 = blockIdx.y * 8;
    const int b = blockIdx.z;

    for (int i = tid; i < 216; i += 256) {
        const int t = i / 8, j = i % 8;
        const uint32_t a0 = __float_as_uint(w[(4 * j) * 27 + t]);
        const uint32_t a1 = __float_as_uint(w[(4 * j + 1) * 27 + t]);
        const uint32_t a2 = __float_as_uint(w[(4 * j + 2) * 27 + t]);
        const uint32_t a3 = __float_as_uint(w[(4 * j + 3) * 27 + t]);
        ulonglong2 e;
        e.x = ((unsigned long long)a1 << 32) | a0;
        e.y = ((unsigned long long)a3 << 32) | a2;
        s_w4[t][j] = e;
    }
    if (tid < 32) s_b[tid] = bias[tid];
    for (int i = tid; i < 1020; i += 256) {
        const int c = i / 340, r = i % 340;
        const int rr = r / 34, cc = r % 34;
        const int gy = y0 - 1 + rr, gx = x0 - 1 + cc;
        float v = 0.f;
        if ((unsigned)gy < HH && (unsigned)gx < WW)
            v = x[((size_t)(b * 3 + c)) * HW + (size_t)gy * WW + gx];
        s_in[c][rr][cc] = v;
    }
    __syncthreads();

    float vin[27];
    #pragma unroll
    for (int c = 0; c < 3; c++)
        #pragma unroll
        for (int dy = 0; dy < 3; dy++)
            #pragma unroll
            for (int dx = 0; dx < 3; dx++)
                vin[c * 9 + dy * 3 + dx] = s_in[c][ty + dy][tx + dx];

    unsigned long long acc2[16];
    #pragma unroll
    for (int j = 0; j < 16; j++) acc2[j] = 0ull;
    #pragma unroll
    for (int t = 0; t < 27; t++) {
        unsigned long long vv;
        asm("mov.b64 %0, {%1, %1};" : "=l"(vv) : "r"(__float_as_uint(vin[t])));
        #pragma unroll
        for (int j = 0; j < 8; j++) {
            const ulonglong2 ww = s_w4[t][j];
            fma2(acc2[2 * j], vv, ww.x);
            fma2(acc2[2 * j + 1], vv, ww.y);
        }
    }

    const float alpha = pr[0];
    uint32_t uu[16];
    #pragma unroll
    for (int j = 0; j < 16; j++) {
        uint32_t lo, hi;
        asm("mov.b64 {%0, %1}, %2;" : "=r"(lo), "=r"(hi) : "l"(acc2[j]));
        float v0 = __uint_as_float(lo) + s_b[2 * j];
        float v1 = __uint_as_float(hi) + s_b[2 * j + 1];
        if (v0 < 0.f) v0 *= alpha;
        if (v1 < 0.f) v1 *= alpha;
        uu[j] = pack_h2(v0, v1);   // natural order
    }
    __half* dst = out + ((size_t)b * HW + (size_t)(y0 + ty) * WW + x0 + tx) * 32;
    #pragma unroll
    for (int q = 0; q < 4; q++)
        ((uint4*)dst)[q] = make_uint4(uu[4 * q], uu[4 * q + 1], uu[4 * q + 2], uu[4 * q + 3]);
}

// ================= GAP partials =================
__global__ __launch_bounds__(256) void gapp_k(const float* __restrict__ hp, float* __restrict__ part)
{
    __shared__ float red[8][12];
    const int b = blockIdx.x, seg = blockIdx.y;
    const int tid = threadIdx.x;
    float s[12];
    #pragma unroll
    for (int c = 0; c < 12; c++) s[c] = 0.f;
    #pragma unroll
    for (int st = 0; st < 3; st++) {
        const float4* base = (const float4*)(hp + st * SST + ((size_t)b * HW + (size_t)seg * (HW / 16)) * 4);
        for (int i = tid; i < HW / 16; i += 256) {
            const float4 q = base[i];
            s[st * 4 + 0] += q.x; s[st * 4 + 1] += q.y;
            s[st * 4 + 2] += q.z; s[st * 4 + 3] += q.w;
        }
    }
    #pragma unroll
    for (int k = 16; k > 0; k >>= 1)
        #pragma unroll
        for (int c = 0; c < 12; c++) s[c] += __shfl_xor_sync(0xffffffffu, s[c], k);
    if ((tid & 31) == 0)
        #pragma unroll
        for (int c = 0; c < 12; c++) red[tid >> 5][c] = s[c];
    __syncthreads();
    if (tid < 12) {
        float t = 0.f;
        #pragma unroll
        for (int wdx = 0; wdx < 8; wdx++) t += red[wdx][tid];
        part[((size_t)b * 16 + seg) * 12 + tid] = t;
    }
}

// ================= fused GAP-combine + SE =================
__global__ void gapse_k(const float* __restrict__ part,
                        const float* __restrict__ c1a, const float* __restrict__ c2a,
                        const float* __restrict__ c1b, const float* __restrict__ c2b,
                        const float* __restrict__ c1c, const float* __restrict__ c2c,
                        float* __restrict__ sout)
{
    __shared__ float gg[8][12];
    __shared__ float tt[8][12];
    const int t = threadIdx.x;
    const int b = t / 12, c = t % 12;
    const int st = c >> 2, c4 = c & 3;
    const float* c1 = (st == 0) ? c1a : (st == 1 ? c1b : c1c);
    const float* c2 = (st == 0) ? c2a : (st == 1 ? c2b : c2c);
    if (t < 96) {
        float s = 0.f;
        #pragma unroll
        for (int k = 0; k < 16; k++) s += part[((size_t)b * 16 + k) * 12 + c];
        gg[b][c] = s * (1.0f / HW);
    }
    __syncthreads();
    if (t < 96) {
        float v = 0.f;
        #pragma unroll
        for (int k = 0; k < 4; k++) v += c1[c4 * 4 + k] * gg[b][st * 4 + k];
        tt[b][c] = fmaxf(v, 0.f);
    }
    __syncthreads();
    if (t < 96) {
        float v = 0.f;
        #pragma unroll
        for (int k = 0; k < 4; k++) v += c2[c4 * 4 + k] * tt[b][st * 4 + k];
        sout[st * 32 + b * 4 + c4] = 1.f / (1.f + __expf(-v));
    }
}

// ================= fused blur + softmax + combine, 64x64 tiles =================
__global__ __launch_bounds__(256) void blurfuse_k(
    const float* __restrict__ src, const float* __restrict__ hp,
    const float* __restrict__ sv, float* __restrict__ out)
{
    extern __shared__ float bsm[];
    float (*s_src)[89] = (float(*)[89])bsm;
    float (*s_h5)[84]  = (float(*)[84])(bsm + 88 * 89);
    float (*s_h15)[64] = (float(*)[64])(bsm + 88 * 89 + 88 * 84);
    float (*s_h25)[64] = (float(*)[64])(bsm + 88 * 89 + 88 * 84 + 88 * 64);

    const int tx = threadIdx.x, ty = threadIdx.y;
    const int tid = ty * 64 + tx;
    const int x0 = blockIdx.x * 64, y0 = blockIdx.y * 64;
    const int z = blockIdx.z;
    const int c = z % 3, b = z / 3;
    const size_t cb = (size_t)(b * 3 + c) * HW;

    for (int i = tid; i < 88 * 88; i += 256) {
        const int r = i / 88, cc = i % 88;
        const int gy = y0 - 12 + r, gx = x0 - 12 + cc;
        float v = 0.f;
        if ((unsigned)gy < HH && (unsigned)gx < WW)
            v = src[cb + (size_t)gy * WW + gx];
        s_src[r][cc] = v;
    }
    __syncthreads();

    for (int i = tid; i < 88 * 84; i += 256) {
        const int r = i / 84, j = i % 84;
        s_h5[r][j] = s_src[r][j] + s_src[r][j + 1] + s_src[r][j + 2]
                   + s_src[r][j + 3] + s_src[r][j + 4];
    }
    __syncthreads();

    for (int i = tid; i < 88 * 64; i += 256) {
        const int r = i / 64, t = i % 64;
        const float h15 = s_h5[r][t + 5] + s_h5[r][t + 10] + s_h5[r][t + 15];
        s_h15[r][t] = h15;
        s_h25[r][t] = h15 + s_h5[r][t] + s_h5[r][t + 20];
    }
    __syncthreads();

    const int r0 = ty * 16 + 12;
    float v5 = 0.f, v15 = 0.f, v25 = 0.f;
    #pragma unroll
    for (int d = -2; d <= 2; d++) v5 += s_h5[r0 + d][tx + 10];
    #pragma unroll
    for (int d = -7; d <= 7; d++) v15 += s_h15[r0 + d][tx];
    #pragma unroll
    for (int d = -12; d <= 12; d++) v25 += s_h25[r0 + d][tx];

    const float s0 = sv[b * 4 + 0], s1 = sv[b * 4 + 1], s2 = sv[b * 4 + 2], s3 = sv[b * 4 + 3];
    const int x = x0 + tx;
    const float4* hppix = (const float4*)(hp + (size_t)b * HW * 4);

    #pragma unroll 1
    for (int j = 0; j < 16; j++) {
        const int y = y0 + ty * 16 + j;
        const int r = r0 + j;
        const float4 hv = hppix[(size_t)y * WW + x];
        float e0 = hv.x * s0, e1 = hv.y * s1, e2 = hv.z * s2, e3 = hv.w * s3;
        float m = fmaxf(fmaxf(e0, e1), fmaxf(e2, e3));
        float w0 = __expf(e0 - m), w1 = __expf(e1 - m), w2 = __expf(e2 - m), w3 = __expf(e3 - m);
        float inv = 1.f / (w0 + w1 + w2 + w3);
        float o = (w0 * inv) * s_src[r][tx + 12]
                + (w1 * inv) * (v5 * (1.f / 25.f))
                + (w2 * inv) * (v15 * (1.f / 225.f))
                + (w3 * inv) * (v25 * (1.f / 625.f));
        out[cb + (size_t)y * WW + x] = o;
        if (j < 15) {
            v5 += s_h5[r + 3][tx + 10] - s_h5[r - 2][tx + 10];
            v15 += s_h15[r + 8][tx] - s_h15[r - 7][tx];
            v25 += s_h25[r + 13][tx] - s_h25[r - 12][tx];
        }
    }
}

// ================= launch =================
extern "C" void kernel_launch(void* const* d_in, const int* in_sizes, int n_in,
                              void* d_out, int out_size)
{
    const float* x   = (const float*)d_in[0];
    const float* bw1 = (const float*)d_in[1];
    const float* bb1 = (const float*)d_in[2];
    const float* a1  = (const float*)d_in[3];
    const float* bw2 = (const float*)d_in[4];
    const float* bb2 = (const float*)d_in[5];
    const float* a2  = (const float*)d_in[6];
    const float* bw3 = (const float*)d_in[7];
    const float* bb3 = (const float*)d_in[8];
    const float* a3  = (const float*)d_in[9];
    const float* hw_[3]  = { (const float*)d_in[10], (const float*)d_in[14], (const float*)d_in[18] };
    const float* hb_[3]  = { (const float*)d_in[11], (const float*)d_in[15], (const float*)d_in[19] };
    const float* hc1_[3] = { (const float*)d_in[12], (const float*)d_in[16], (const float*)d_in[20] };
    const float* hc2_[3] = { (const float*)d_in[13], (const float*)d_in[17], (const float*)d_in[21] };

    float *B1, *B2, *P, *S, *TX, *TX2;
    uint2 *W2p, *W3p, *WHp;
    cudaGetSymbolAddress((void**)&B1, g_B1);
    cudaGetSymbolAddress((void**)&B2, g_B2);
    cudaGetSymbolAddress((void**)&P, g_P);
    cudaGetSymbolAddress((void**)&S, g_S);
    cudaGetSymbolAddress((void**)&TX, g_TX);
    cudaGetSymbolAddress((void**)&TX2, g_TX2);
    cudaGetSymbolAddress((void**)&W2p, g_W2);
    cudaGetSymbolAddress((void**)&W3p, g_W3);
    cudaGetSymbolAddress((void**)&WHp, g_WH);
    __half* B1h = (__half*)B1;
    __half* B2h = (__half*)B2;

    const int smem2 = 4 * 2 * 258 * 32 + 9 * 2 * 64 * 32;  // 102912
    const int smem3 = 4 * 4 * 130 * 32 + 9 * 4 * 32 * 32;  // 103424
    const int smemH = 4 * 2 * 258 * 32 + 9 * 2 * 16 * 32;  // 75264
    const int smemF = (88 * 89 + 88 * 84 + 2 * 88 * 64) * 4;  // 105952
    cudaFuncSetAttribute((const void*)mconv_k<32, 64, 4, 4, 4, false>,
                         cudaFuncAttributeMaxDynamicSharedMemorySize, smem2);
    cudaFuncSetAttribute((const void*)mconv_k<64, 32, 4, 2, 2, false>,
                         cudaFuncAttributeMaxDynamicSharedMemorySize, smem3);
    cudaFuncSetAttribute((const void*)mconv_k<32, 16, 8, 2, 2, true>,
                         cudaFuncAttributeMaxDynamicSharedMemorySize, smemH);
    cudaFuncSetAttribute((const void*)blurfuse_k,
                         cudaFuncAttributeMaxDynamicSharedMemorySize, smemF);

    // ---- weight pre-transform ----
    wprep_k<<<(4608 + 4608 + 1152 + 255) / 256, 256>>>(bw2, bw3, hw_[0], hw_[1], hw_[2],
                                                       W2p, W3p, WHp);

    // ---- body ----
    conv1_k<<<dim3(16, 64, BB), 256>>>(x, bw1, bb1, a1, B1h);
    mconv_k<32, 64, 4, 4, 4, false><<<dim3(2, 64, BB), 256, smem2>>>(
        B1h, W2p, bb2, nullptr, nullptr, a2, B2h);
    mconv_k<64, 32, 4, 2, 2, false><<<dim3(4, 64, BB), 256, smem3>>>(
        B2h, W3p, bb3, nullptr, nullptr, a3, B1h);

    // ---- heads -> 3 packed stage buffers ----
    float* HP = B2;
    mconv_k<32, 16, 8, 2, 2, true><<<dim3(2, 64, BB), 256, smemH>>>(
        B1h, WHp, hb_[0], hb_[1], hb_[2], nullptr, HP);
    gapp_k<<<dim3(BB, 16), 256>>>(HP, P);
    gapse_k<<<1, 96>>>(P, hc1_[0], hc2_[0], hc1_[1], hc2_[1], hc1_[2], hc2_[2], S);

    // ---- fused blur+softmax+combine (ping-pong) ----
    const dim3 fgrid(8, 8, BB * 3);
    const dim3 fblk(64, 4);
    blurfuse_k<<<fgrid, fblk, smemF>>>(x,   HP + 0 * SST, S + 0,  TX);
    blurfuse_k<<<fgrid, fblk, smemF>>>(TX,  HP + 1 * SST, S + 32, TX2);
    blurfuse_k<<<fgrid, fblk, smemF>>>(TX2, HP + 2 * SST, S + 64, (float*)d_out);
    (void)in_sizes; (void)n_in; (void)out_size;
}

// round 11
// speedup vs baseline: 1.1771x; 1.1771x over previous
#include <cuda_runtime.h>
#include <cuda_fp16.h>
#include <cstdint>
#include <cstddef>

#define HH 512
#define WW 512
#define BB 8
constexpr int HW = HH * WW;
constexpr size_t SST = (size_t)BB * HW * 4;   // floats per head-stage buffer

// ---------------- scratch ----------------
__device__ float g_B1[(size_t)BB * HW * 32 / 2];   // fp16 NHWC 32ch (natural order)
__device__ float g_B2[(size_t)BB * HW * 64];       // fp16 64ch / 3x packed HP stage buffers
__device__ float g_P[BB * 16 * 12];
__device__ float g_S[3 * BB * 4];
__device__ float g_TX[(size_t)BB * 3 * HW];
__device__ float g_TX2[(size_t)BB * 3 * HW];
__device__ uint2 g_W2[9 * 2 * 64 * 4];
__device__ uint2 g_W3[9 * 4 * 32 * 4];
__device__ uint2 g_WH[9 * 2 * 16 * 4];

// ---------------- helpers ----------------
__device__ __forceinline__ uint32_t smem_u32(const void* p) {
    uint32_t r;
    asm("{ .reg .u64 t; cvta.to.shared.u64 t, %1; cvt.u32.u64 %0, t; }" : "=r"(r) : "l"(p));
    return r;
}
__device__ __forceinline__ uint32_t pack_h2(float a, float b) {
    __half2 h = __floats2half2_rn(a, b);
    return *(uint32_t*)&h;
}
__device__ __forceinline__ void mma16(float* d, uint32_t a0, uint32_t a1, uint32_t a2,
                                      uint32_t a3, uint32_t b0, uint32_t b1) {
    asm volatile(
        "mma.sync.aligned.m16n8k16.row.col.f32.f16.f16.f32 "
        "{%0,%1,%2,%3}, {%4,%5,%6,%7}, {%8,%9}, {%0,%1,%2,%3};"
        : "+f"(d[0]), "+f"(d[1]), "+f"(d[2]), "+f"(d[3])
        : "r"(a0), "r"(a1), "r"(a2), "r"(a3), "r"(b0), "r"(b1));
}
__device__ __forceinline__ void ldsm4(uint32_t* r, uint32_t addr) {
    asm volatile("ldmatrix.sync.aligned.m8n8.x4.shared.b16 {%0,%1,%2,%3}, [%4];"
                 : "=r"(r[0]), "=r"(r[1]), "=r"(r[2]), "=r"(r[3]) : "r"(addr));
}
__device__ __forceinline__ void fma2(unsigned long long& d, unsigned long long a,
                                     unsigned long long b) {
    asm("fma.rn.f32x2 %0, %1, %2, %0;" : "+l"(d) : "l"(a), "l"(b));
}
#define CP_A16(dst, src) asm volatile("cp.async.ca.shared.global [%0], [%1], 16;" :: "r"(dst), "l"(src) : "memory")
#define CP_COMMIT()      asm volatile("cp.async.commit_group;" ::: "memory")
#define CP_WAIT0()       asm volatile("cp.async.wait_group 0;" ::: "memory")
#define STZ16(dst)       asm volatile("st.shared.v4.b32 [%0], {%1,%1,%1,%1};" :: "r"(dst), "r"(0u) : "memory")

// pixel-half swizzle: physical 16B-half of pixel p, logical half h
__device__ __forceinline__ uint32_t psw(int p, int h) {
    return (uint32_t)(p * 32 + ((h ^ ((p >> 2) & 1)) << 4));
}

// ================= fused weight pre-transform =================
__device__ void wprep_one(const float* wA, const float* wB2, const float* wC,
                          int CIN, int NTOT, int H3, uint2* out, int i)
{
    const int NKS = CIN / 16;
    const int tap = i / (NKS * NTOT * 4);
    int r = i % (NKS * NTOT * 4);
    const int ks = r / (NTOT * 4);
    r %= NTOT * 4;
    const int n = r >> 2, t4 = r & 3;
    float v0 = 0.f, v1 = 0.f, v2 = 0.f, v3 = 0.f;
    const int cb = ks * 16 + t4 * 2;
    if (H3) {
        if (n < 12) {
            const float* wp = (n < 4) ? wA : (n < 8 ? wB2 : wC);
            const size_t nb = (size_t)(n & 3) * CIN;
            v0 = wp[(nb + cb) * 9 + tap];
            v1 = wp[(nb + cb + 1) * 9 + tap];
            v2 = wp[(nb + cb + 8) * 9 + tap];
            v3 = wp[(nb + cb + 9) * 9 + tap];
        }
    } else {
        const size_t nb = (size_t)n * CIN;
        v0 = wA[(nb + cb) * 9 + tap];
        v1 = wA[(nb + cb + 1) * 9 + tap];
        v2 = wA[(nb + cb + 8) * 9 + tap];
        v3 = wA[(nb + cb + 9) * 9 + tap];
    }
    uint2 e;
    e.x = pack_h2(v0, v1);
    e.y = pack_h2(v2, v3);
    out[i] = e;
}

__global__ void wprep_k(const float* __restrict__ w2, const float* __restrict__ w3,
                        const float* __restrict__ hA, const float* __restrict__ hB,
                        const float* __restrict__ hC,
                        uint2* __restrict__ o2, uint2* __restrict__ o3, uint2* __restrict__ oH)
{
    constexpr int T2 = 9 * 2 * 64 * 4;
    constexpr int T3 = 9 * 4 * 32 * 4;
    constexpr int TH = 9 * 2 * 16 * 4;
    int i = blockIdx.x * 256 + threadIdx.x;
    if (i < T2) { wprep_one(w2, nullptr, nullptr, 32, 64, 0, o2, i); return; }
    i -= T2;
    if (i < T3) { wprep_one(w3, nullptr, nullptr, 64, 32, 0, o3, i); return; }
    i -= T3;
    if (i < TH) { wprep_one(hA, hB, hC, 32, 16, 1, oH, i); }
}

// ================= fp16 m16n8k16 3x3 conv (swizzled ldmatrix A fragments) =================
template<int CIN, int NTOT, int MW, int MT, int NT, bool H3>
__global__ __launch_bounds__(256) void mconv_k(
    const __half* __restrict__ in, const uint2* __restrict__ wp,
    const float* __restrict__ bA, const float* __restrict__ bB2, const float* __restrict__ bC,
    const float* __restrict__ pr, void* __restrict__ outv)
{
    constexpr int P = MW * MT * 16;
    constexpr int PP = P + 2;
    constexpr int NKS = CIN / 16;
    constexpr int SEGS = 2 * NKS;
    constexpr int SLOTU2 = NKS * PP * 4;
    constexpr int WSEGS = 9 * NKS * NTOT * 2;

    extern __shared__ __align__(16) char smraw[];
    const uint2* w_u2 = (const uint2*)smraw + 4 * SLOTU2;
    const uint32_t a_u = smem_u32(smraw);
    const uint32_t w_addr = a_u + (uint32_t)(4 * SLOTU2 * 8);

    const int tid = threadIdx.x;
    const int lane = tid & 31;
    const int wid = tid >> 5;
    const int g = lane >> 2, tg = lane & 3;
    const int lrow = lane & 15, lhalf = lane >> 4;
    const int mbase = (wid % MW) * MT * 16;
    const int nbase = (wid / MW) * NT * 8;
    const int x0 = blockIdx.x * P;
    const int y0 = blockIdx.y * 8;
    const int b = blockIdx.z;

    const __half* inb = in + (size_t)b * HW * CIN;

    auto stage = [&](int yy) {
        const int slot = (yy + 4) & 3;
        const uint32_t sbase = a_u + (uint32_t)(slot * SLOTU2 * 8);
        const bool rok = ((unsigned)yy < HH);
        const __half* rowp = inb + (size_t)yy * WW * CIN;
        for (int i = tid; i < PP * SEGS; i += 256) {
            const int p = i / SEGS;
            const int s = i % SEGS;
            const int ks = s >> 1, h = s & 1;
            const int gx = x0 + p - 1;
            const uint32_t dst = sbase + (uint32_t)(ks * PP * 32) + psw(p, h);
            if (rok && (unsigned)gx < WW)
                CP_A16(dst, rowp + (size_t)gx * CIN + ks * 16 + h * 8);
            else
                STZ16(dst);
        }
    };

    for (int i = tid; i < WSEGS; i += 256)
        CP_A16(w_addr + (uint32_t)i * 16, (const char*)wp + (size_t)i * 16);
    stage(y0 - 1); stage(y0); stage(y0 + 1);
    CP_COMMIT();

    __half* obH = (__half*)outv + (size_t)b * HW * NTOT;
    const float alpha = pr ? pr[0] : 0.f;
    const int pb0 = mbase + lrow;

    #pragma unroll 1
    for (int yi = 0; yi < 8; yi++) {
        const int y = y0 + yi;
        CP_WAIT0();
        __syncthreads();
        if (yi < 7) { stage(y + 2); CP_COMMIT(); }

        float acc[MT][NT][4];
        #pragma unroll
        for (int mt = 0; mt < MT; mt++)
            #pragma unroll
            for (int nt = 0; nt < NT; nt++)
                #pragma unroll
                for (int e = 0; e < 4; e++) acc[mt][nt][e] = 0.f;

        #pragma unroll 1
        for (int tap = 0; tap < 9; tap++) {
            const int dy = tap / 3, dx = tap - dy * 3;
            const int slot = (y + dy + 3) & 3;
            #pragma unroll
            for (int ks = 0; ks < NKS; ks++) {
                const uint32_t kbase = a_u + (uint32_t)(((slot * NKS + ks) * PP) * 32);
                uint32_t m[MT][4];
                #pragma unroll
                for (int mt = 0; mt < MT; mt++) {
                    const int p = pb0 + mt * 16 + dx;
                    ldsm4(m[mt], kbase + psw(p, lhalf));
                }
                #pragma unroll
                for (int nt = 0; nt < NT; nt++) {
                    const uint2 qw = w_u2[((tap * NKS + ks) * NTOT + nbase + nt * 8 + g) * 4 + tg];
                    #pragma unroll
                    for (int mt = 0; mt < MT; mt++)
                        mma16(acc[mt][nt], m[mt][0], m[mt][1], m[mt][2], m[mt][3], qw.x, qw.y);
                }
            }
        }

        // ---- epilogue (natural NHWC) ----
        #pragma unroll
        for (int mt = 0; mt < MT; mt++) {
            const int px = x0 + mbase + mt * 16 + g;
            #pragma unroll
            for (int nt = 0; nt < NT; nt++) {
                const int ch = nbase + nt * 8 + tg * 2;   // even
                if (H3) {
                    if (ch < 12) {
                        const int st = ch >> 2, c4 = ch & 3;
                        const float* bp = (st == 0) ? bA : (st == 1 ? bB2 : bC);
                        const float bv0 = bp[c4], bv1 = bp[c4 + 1];
                        float* hb = (float*)outv + st * SST + (size_t)b * HW * 4;
                        float2 lo = make_float2(acc[mt][nt][0] + bv0, acc[mt][nt][1] + bv1);
                        float2 hi = make_float2(acc[mt][nt][2] + bv0, acc[mt][nt][3] + bv1);
                        *(float2*)(hb + ((size_t)y * WW + px) * 4 + c4) = lo;
                        *(float2*)(hb + ((size_t)y * WW + px + 8) * 4 + c4) = hi;
                    }
                } else {
                    const float bv0 = bA[ch], bv1 = bA[ch + 1];
                    float v0 = acc[mt][nt][0] + bv0;
                    float v1 = acc[mt][nt][1] + bv1;
                    float v2 = acc[mt][nt][2] + bv0;
                    float v3 = acc[mt][nt][3] + bv1;
                    if (v0 < 0.f) v0 *= alpha;
                    if (v1 < 0.f) v1 *= alpha;
                    if (v2 < 0.f) v2 *= alpha;
                    if (v3 < 0.f) v3 *= alpha;
                    *(uint32_t*)(obH + ((size_t)y * WW + px) * NTOT + ch) = pack_h2(v0, v1);
                    *(uint32_t*)(obH + ((size_t)y * WW + px + 8) * NTOT + ch) = pack_h2(v2, v3);
                }
            }
        }
    }
}

// ================= conv1: 3->32, f32x2 FMA + LDS.128 weights, natural NHWC out =================
__global__ __launch_bounds__(256) void conv1_k(
    const float* __restrict__ x, const float* __restrict__ w,
    const float* __restrict__ bias, const float* __restrict__ pr,
    __half* __restrict__ out)
{
    __shared__ float s_in[3][10][34];
    __shared__ ulonglong2 s_w4[27][8];
    __shared__ float s_b[32];

    const int tid = threadIdx.x;
    const int tx = tid & 31, ty = tid >> 5;
    const int x0 = blockIdx.x * 32, y0 = blockIdx.y * 8;
    const int b = blockIdx.z;

    for (int i = tid; i < 216; i += 256) {
        const int t = i / 8, j = i % 8;
        const uint32_t a0 = __float_as_uint(w[(4 * j) * 27 + t]);
        const uint32_t a1 = __float_as_uint(w[(4 * j + 1) * 27 + t]);
        const uint32_t a2 = __float_as_uint(w[(4 * j + 2) * 27 + t]);
        const uint32_t a3 = __float_as_uint(w[(4 * j + 3) * 27 + t]);
        ulonglong2 e;
        e.x = ((unsigned long long)a1 << 32) | a0;
        e.y = ((unsigned long long)a3 << 32) | a2;
        s_w4[t][j] = e;
    }
    if (tid < 32) s_b[tid] = bias[tid];
    for (int i = tid; i < 1020; i += 256) {
        const int c = i / 340, r = i % 340;
        const int rr = r / 34, cc = r % 34;
        const int gy = y0 - 1 + rr, gx = x0 - 1 + cc;
        float v = 0.f;
        if ((unsigned)gy < HH && (unsigned)gx < WW)
            v = x[((size_t)(b * 3 + c)) * HW + (size_t)gy * WW + gx];
        s_in[c][rr][cc] = v;
    }
    __syncthreads();

    float vin[27];
    #pragma unroll
    for (int c = 0; c < 3; c++)
        #pragma unroll
        for (int dy = 0; dy < 3; dy++)
            #pragma unroll
            for (int dx = 0; dx < 3; dx++)
                vin[c * 9 + dy * 3 + dx] = s_in[c][ty + dy][tx + dx];

    unsigned long long acc2[16];
    #pragma unroll
    for (int j = 0; j < 16; j++) acc2[j] = 0ull;
    #pragma unroll
    for (int t = 0; t < 27; t++) {
        unsigned long long vv;
        asm("mov.b64 %0, {%1, %1};" : "=l"(vv) : "r"(__float_as_uint(vin[t])));
        #pragma unroll
        for (int j = 0; j < 8; j++) {
            const ulonglong2 ww = s_w4[t][j];
            fma2(acc2[2 * j], vv, ww.x);
            fma2(acc2[2 * j + 1], vv, ww.y);
        }
    }

    const float alpha = pr[0];
    uint32_t uu[16];
    #pragma unroll
    for (int j = 0; j < 16; j++) {
        uint32_t lo, hi;
        asm("mov.b64 {%0, %1}, %2;" : "=r"(lo), "=r"(hi) : "l"(acc2[j]));
        float v0 = __uint_as_float(lo) + s_b[2 * j];
        float v1 = __uint_as_float(hi) + s_b[2 * j + 1];
        if (v0 < 0.f) v0 *= alpha;
        if (v1 < 0.f) v1 *= alpha;
        uu[j] = pack_h2(v0, v1);
    }
    __half* dst = out + ((size_t)b * HW + (size_t)(y0 + ty) * WW + x0 + tx) * 32;
    #pragma unroll
    for (int q = 0; q < 4; q++)
        ((uint4*)dst)[q] = make_uint4(uu[4 * q], uu[4 * q + 1], uu[4 * q + 2], uu[4 * q + 3]);
}

// ================= GAP partials =================
__global__ __launch_bounds__(256) void gapp_k(const float* __restrict__ hp, float* __restrict__ part)
{
    __shared__ float red[8][12];
    const int b = blockIdx.x, seg = blockIdx.y;
    const int tid = threadIdx.x;
    float s[12];
    #pragma unroll
    for (int c = 0; c < 12; c++) s[c] = 0.f;
    #pragma unroll
    for (int st = 0; st < 3; st++) {
        const float4* base = (const float4*)(hp + st * SST + ((size_t)b * HW + (size_t)seg * (HW / 16)) * 4);
        for (int i = tid; i < HW / 16; i += 256) {
            const float4 q = base[i];
            s[st * 4 + 0] += q.x; s[st * 4 + 1] += q.y;
            s[st * 4 + 2] += q.z; s[st * 4 + 3] += q.w;
        }
    }
    #pragma unroll
    for (int k = 16; k > 0; k >>= 1)
        #pragma unroll
        for (int c = 0; c < 12; c++) s[c] += __shfl_xor_sync(0xffffffffu, s[c], k);
    if ((tid & 31) == 0)
        #pragma unroll
        for (int c = 0; c < 12; c++) red[tid >> 5][c] = s[c];
    __syncthreads();
    if (tid < 12) {
        float t = 0.f;
        #pragma unroll
        for (int wdx = 0; wdx < 8; wdx++) t += red[wdx][tid];
        part[((size_t)b * 16 + seg) * 12 + tid] = t;
    }
}

// ================= fused GAP-combine + SE =================
__global__ void gapse_k(const float* __restrict__ part,
                        const float* __restrict__ c1a, const float* __restrict__ c2a,
                        const float* __restrict__ c1b, const float* __restrict__ c2b,
                        const float* __restrict__ c1c, const float* __restrict__ c2c,
                        float* __restrict__ sout)
{
    __shared__ float gg[8][12];
    __shared__ float tt[8][12];
    const int t = threadIdx.x;
    const int b = t / 12, c = t % 12;
    const int st = c >> 2, c4 = c & 3;
    const float* c1 = (st == 0) ? c1a : (st == 1 ? c1b : c1c);
    const float* c2 = (st == 0) ? c2a : (st == 1 ? c2b : c2c);
    if (t < 96) {
        float s = 0.f;
        #pragma unroll
        for (int k = 0; k < 16; k++) s += part[((size_t)b * 16 + k) * 12 + c];
        gg[b][c] = s * (1.0f / HW);
    }
    __syncthreads();
    if (t < 96) {
        float v = 0.f;
        #pragma unroll
        for (int k = 0; k < 4; k++) v += c1[c4 * 4 + k] * gg[b][st * 4 + k];
        tt[b][c] = fmaxf(v, 0.f);
    }
    __syncthreads();
    if (t < 96) {
        float v = 0.f;
        #pragma unroll
        for (int k = 0; k < 4; k++) v += c2[c4 * 4 + k] * tt[b][st * 4 + k];
        sout[st * 32 + b * 4 + c4] = 1.f / (1.f + __expf(-v));
    }
}

// ================= fused blur + softmax + combine, 64x64 tiles =================
__global__ __launch_bounds__(256) void blurfuse_k(
    const float* __restrict__ src, const float* __restrict__ hp,
    const float* __restrict__ sv, float* __restrict__ out)
{
    extern __shared__ float bsm[];
    float (*s_src)[89] = (float(*)[89])bsm;
    float (*s_h5)[84]  = (float(*)[84])(bsm + 88 * 89);
    float (*s_h15)[64] = (float(*)[64])(bsm + 88 * 89 + 88 * 84);
    float (*s_h25)[64] = (float(*)[64])(bsm + 88 * 89 + 88 * 84 + 88 * 64);

    const int tx = threadIdx.x, ty = threadIdx.y;
    const int tid = ty * 64 + tx;
    const int x0 = blockIdx.x * 64, y0 = blockIdx.y * 64;
    const int z = blockIdx.z;
    const int c = z % 3, b = z / 3;
    const size_t cb = (size_t)(b * 3 + c) * HW;

    for (int i = tid; i < 88 * 88; i += 256) {
        const int r = i / 88, cc = i % 88;
        const int gy = y0 - 12 + r, gx = x0 - 12 + cc;
        float v = 0.f;
        if ((unsigned)gy < HH && (unsigned)gx < WW)
            v = src[cb + (size_t)gy * WW + gx];
        s_src[r][cc] = v;
    }
    __syncthreads();

    for (int i = tid; i < 88 * 84; i += 256) {
        const int r = i / 84, j = i % 84;
        s_h5[r][j] = s_src[r][j] + s_src[r][j + 1] + s_src[r][j + 2]
                   + s_src[r][j + 3] + s_src[r][j + 4];
    }
    __syncthreads();

    for (int i = tid; i < 88 * 64; i += 256) {
        const int r = i / 64, t = i % 64;
        const float h15 = s_h5[r][t + 5] + s_h5[r][t + 10] + s_h5[r][t + 15];
        s_h15[r][t] = h15;
        s_h25[r][t] = h15 + s_h5[r][t] + s_h5[r][t + 20];
    }
    __syncthreads();

    const int r0 = ty * 16 + 12;
    float v5 = 0.f, v15 = 0.f, v25 = 0.f;
    #pragma unroll
    for (int d = -2; d <= 2; d++) v5 += s_h5[r0 + d][tx + 10];
    #pragma unroll
    for (int d = -7; d <= 7; d++) v15 += s_h15[r0 + d][tx];
    #pragma unroll
    for (int d = -12; d <= 12; d++) v25 += s_h25[r0 + d][tx];

    const float s0 = sv[b * 4 + 0], s1 = sv[b * 4 + 1], s2 = sv[b * 4 + 2], s3 = sv[b * 4 + 3];
    const int x = x0 + tx;
    const float4* hppix = (const float4*)(hp + (size_t)b * HW * 4);

    #pragma unroll 1
    for (int j = 0; j < 16; j++) {
        const int y = y0 + ty * 16 + j;
        const int r = r0 + j;
        const float4 hv = hppix[(size_t)y * WW + x];
        float e0 = hv.x * s0, e1 = hv.y * s1, e2 = hv.z * s2, e3 = hv.w * s3;
        float m = fmaxf(fmaxf(e0, e1), fmaxf(e2, e3));
        float w0 = __expf(e0 - m), w1 = __expf(e1 - m), w2 = __expf(e2 - m), w3 = __expf(e3 - m);
        float inv = 1.f / (w0 + w1 + w2 + w3);
        float o = (w0 * inv) * s_src[r][tx + 12]
                + (w1 * inv) * (v5 * (1.f / 25.f))
                + (w2 * inv) * (v15 * (1.f / 225.f))
                + (w3 * inv) * (v25 * (1.f / 625.f));
        out[cb + (size_t)y * WW + x] = o;
        if (j < 15) {
            v5 += s_h5[r + 3][tx + 10] - s_h5[r - 2][tx + 10];
            v15 += s_h15[r + 8][tx] - s_h15[r - 7][tx];
            v25 += s_h25[r + 13][tx] - s_h25[r - 12][tx];
        }
    }
}

// ================= launch =================
extern "C" void kernel_launch(void* const* d_in, const int* in_sizes, int n_in,
                              void* d_out, int out_size)
{
    const float* x   = (const float*)d_in[0];
    const float* bw1 = (const float*)d_in[1];
    const float* bb1 = (const float*)d_in[2];
    const float* a1  = (const float*)d_in[3];
    const float* bw2 = (const float*)d_in[4];
    const float* bb2 = (const float*)d_in[5];
    const float* a2  = (const float*)d_in[6];
    const float* bw3 = (const float*)d_in[7];
    const float* bb3 = (const float*)d_in[8];
    const float* a3  = (const float*)d_in[9];
    const float* hw_[3]  = { (const float*)d_in[10], (const float*)d_in[14], (const float*)d_in[18] };
    const float* hb_[3]  = { (const float*)d_in[11], (const float*)d_in[15], (const float*)d_in[19] };
    const float* hc1_[3] = { (const float*)d_in[12], (const float*)d_in[16], (const float*)d_in[20] };
    const float* hc2_[3] = { (const float*)d_in[13], (const float*)d_in[17], (const float*)d_in[21] };

    float *B1, *B2, *P, *S, *TX, *TX2;
    uint2 *W2p, *W3p, *WHp;
    cudaGetSymbolAddress((void**)&B1, g_B1);
    cudaGetSymbolAddress((void**)&B2, g_B2);
    cudaGetSymbolAddress((void**)&P, g_P);
    cudaGetSymbolAddress((void**)&S, g_S);
    cudaGetSymbolAddress((void**)&TX, g_TX);
    cudaGetSymbolAddress((void**)&TX2, g_TX2);
    cudaGetSymbolAddress((void**)&W2p, g_W2);
    cudaGetSymbolAddress((void**)&W3p, g_W3);
    cudaGetSymbolAddress((void**)&WHp, g_WH);
    __half* B1h = (__half*)B1;
    __half* B2h = (__half*)B2;

    const int smem2 = 4 * 2 * 258 * 32 + 9 * 2 * 64 * 32;  // 102912
    const int smem3 = 4 * 4 * 130 * 32 + 9 * 4 * 32 * 32;  // 103424
    const int smemH = 4 * 2 * 258 * 32 + 9 * 2 * 16 * 32;  // 75264
    const int smemF = (88 * 89 + 88 * 84 + 2 * 88 * 64) * 4;  // 105952
    cudaFuncSetAttribute((const void*)mconv_k<32, 64, 4, 4, 4, false>,
                         cudaFuncAttributeMaxDynamicSharedMemorySize, smem2);
    cudaFuncSetAttribute((const void*)mconv_k<64, 32, 4, 2, 2, false>,
                         cudaFuncAttributeMaxDynamicSharedMemorySize, smem3);
    cudaFuncSetAttribute((const void*)mconv_k<32, 16, 8, 2, 2, true>,
                         cudaFuncAttributeMaxDynamicSharedMemorySize, smemH);
    cudaFuncSetAttribute((const void*)blurfuse_k,
                         cudaFuncAttributeMaxDynamicSharedMemorySize, smemF);

    // ---- weight pre-transform ----
    wprep_k<<<(4608 + 4608 + 1152 + 255) / 256, 256>>>(bw2, bw3, hw_[0], hw_[1], hw_[2],
                                                       W2p, W3p, WHp);

    // ---- body ----
    conv1_k<<<dim3(16, 64, BB), 256>>>(x, bw1, bb1, a1, B1h);
    mconv_k<32, 64, 4, 4, 4, false><<<dim3(2, 64, BB), 256, smem2>>>(
        B1h, W2p, bb2, nullptr, nullptr, a2, B2h);
    mconv_k<64, 32, 4, 2, 2, false><<<dim3(4, 64, BB), 256, smem3>>>(
        B2h, W3p, bb3, nullptr, nullptr, a3, B1h);

    // ---- heads -> 3 packed stage buffers ----
    float* HP = B2;
    mconv_k<32, 16, 8, 2, 2, true><<<dim3(2, 64, BB), 256, smemH>>>(
        B1h, WHp, hb_[0], hb_[1], hb_[2], nullptr, HP);
    gapp_k<<<dim3(BB, 16), 256>>>(HP, P);
    gapse_k<<<1, 96>>>(P, hc1_[0], hc2_[0], hc1_[1], hc2_[1], hc1_[2], hc2_[2], S);

    // ---- fused blur+softmax+combine (ping-pong) ----
    const dim3 fgrid(8, 8, BB * 3);
    const dim3 fblk(64, 4);
    blurfuse_k<<<fgrid, fblk, smemF>>>(x,   HP + 0 * SST, S + 0,  TX);
    blurfuse_k<<<fgrid, fblk, smemF>>>(TX,  HP + 1 * SST, S + 32, TX2);
    blurfuse_k<<<fgrid, fblk, smemF>>>(TX2, HP + 2 * SST, S + 64, (float*)d_out);
    (void)in_sizes; (void)n_in; (void)out_size;
}

// round 12
// speedup vs baseline: 1.2335x; 1.0479x over previous
#include <cuda_runtime.h>
#include <cuda_fp16.h>
#include <cstdint>
#include <cstddef>

#define HH 512
#define WW 512
#define BB 8
constexpr int HW = HH * WW;
constexpr size_t SST = (size_t)BB * HW * 4;   // floats per head-stage buffer

// ---------------- scratch ----------------
__device__ float g_B1[(size_t)BB * HW * 32 / 2];   // fp16 NHWC 32ch
__device__ float g_B2[(size_t)BB * HW * 64];       // fp16 64ch / 3x packed HP stage buffers
__device__ float g_P[BB * 16 * 12];
__device__ float g_S[3 * BB * 4];
__device__ float g_TX[(size_t)BB * 3 * HW];
__device__ float g_TX2[(size_t)BB * 3 * HW];
__device__ uint2 g_W2[9 * 2 * 64 * 4];
__device__ uint2 g_W3[9 * 4 * 32 * 4];
__device__ uint2 g_WH[9 * 2 * 16 * 4];

// ---------------- helpers ----------------
__device__ __forceinline__ uint32_t smem_u32(const void* p) {
    uint32_t r;
    asm("{ .reg .u64 t; cvta.to.shared.u64 t, %1; cvt.u32.u64 %0, t; }" : "=r"(r) : "l"(p));
    return r;
}
__device__ __forceinline__ uint32_t pack_h2(float a, float b) {
    __half2 h = __floats2half2_rn(a, b);
    return *(uint32_t*)&h;
}
__device__ __forceinline__ void mma16(float* d, uint32_t a0, uint32_t a1, uint32_t a2,
                                      uint32_t a3, uint32_t b0, uint32_t b1) {
    asm volatile(
        "mma.sync.aligned.m16n8k16.row.col.f32.f16.f16.f32 "
        "{%0,%1,%2,%3}, {%4,%5,%6,%7}, {%8,%9}, {%0,%1,%2,%3};"
        : "+f"(d[0]), "+f"(d[1]), "+f"(d[2]), "+f"(d[3])
        : "r"(a0), "r"(a1), "r"(a2), "r"(a3), "r"(b0), "r"(b1));
}
__device__ __forceinline__ void ldsm4(uint32_t* r, uint32_t addr) {
    asm volatile("ldmatrix.sync.aligned.m8n8.x4.shared.b16 {%0,%1,%2,%3}, [%4];"
                 : "=r"(r[0]), "=r"(r[1]), "=r"(r[2]), "=r"(r[3]) : "r"(addr));
}
__device__ __forceinline__ void fma2(unsigned long long& d, unsigned long long a,
                                     unsigned long long b) {
    asm("fma.rn.f32x2 %0, %1, %2, %0;" : "+l"(d) : "l"(a), "l"(b));
}
#define CP_A16(dst, src) asm volatile("cp.async.ca.shared.global [%0], [%1], 16;" :: "r"(dst), "l"(src) : "memory")
#define CP_COMMIT()      asm volatile("cp.async.commit_group;" ::: "memory")
#define CP_WAIT0()       asm volatile("cp.async.wait_group 0;" ::: "memory")
#define STZ16(dst)       asm volatile("st.shared.v4.b32 [%0], {%1,%1,%1,%1};" :: "r"(dst), "r"(0u) : "memory")

// pixel-half swizzle: physical 16B-half of pixel p, logical half h (bank-conflict-free ldmatrix)
__device__ __forceinline__ uint32_t psw(int p, int h) {
    return (uint32_t)(p * 32 + ((h ^ ((p >> 2) & 1)) << 4));
}

// ================= fused weight pre-transform =================
__device__ void wprep_one(const float* wA, const float* wB2, const float* wC,
                          int CIN, int NTOT, int H3, uint2* out, int i)
{
    const int NKS = CIN / 16;
    const int tap = i / (NKS * NTOT * 4);
    int r = i % (NKS * NTOT * 4);
    const int ks = r / (NTOT * 4);
    r %= NTOT * 4;
    const int n = r >> 2, t4 = r & 3;
    float v0 = 0.f, v1 = 0.f, v2 = 0.f, v3 = 0.f;
    const int cb = ks * 16 + t4 * 2;
    if (H3) {
        if (n < 12) {
            const float* wp = (n < 4) ? wA : (n < 8 ? wB2 : wC);
            const size_t nb = (size_t)(n & 3) * CIN;
            v0 = wp[(nb + cb) * 9 + tap];
            v1 = wp[(nb + cb + 1) * 9 + tap];
            v2 = wp[(nb + cb + 8) * 9 + tap];
            v3 = wp[(nb + cb + 9) * 9 + tap];
        }
    } else {
        const size_t nb = (size_t)n * CIN;
        v0 = wA[(nb + cb) * 9 + tap];
        v1 = wA[(nb + cb + 1) * 9 + tap];
        v2 = wA[(nb + cb + 8) * 9 + tap];
        v3 = wA[(nb + cb + 9) * 9 + tap];
    }
    uint2 e;
    e.x = pack_h2(v0, v1);
    e.y = pack_h2(v2, v3);
    out[i] = e;
}

__global__ void wprep_k(const float* __restrict__ w2, const float* __restrict__ w3,
                        const float* __restrict__ hA, const float* __restrict__ hB,
                        const float* __restrict__ hC,
                        uint2* __restrict__ o2, uint2* __restrict__ o3, uint2* __restrict__ oH)
{
    constexpr int T2 = 9 * 2 * 64 * 4;
    constexpr int T3 = 9 * 4 * 32 * 4;
    constexpr int TH = 9 * 2 * 16 * 4;
    int i = blockIdx.x * 256 + threadIdx.x;
    if (i < T2) { wprep_one(w2, nullptr, nullptr, 32, 64, 0, o2, i); return; }
    i -= T2;
    if (i < T3) { wprep_one(w3, nullptr, nullptr, 64, 32, 0, o3, i); return; }
    i -= T3;
    if (i < TH) { wprep_one(hA, hB, hC, 32, 16, 1, oH, i); }
}

// ================= fp16 m16n8k16 3x3 conv (swizzled ldmatrix, optional row-pairing) =================
template<int CIN, int NTOT, int MW, int MT, int NT, bool H3, int GRP>
__global__ __launch_bounds__(256) void mconv_k(
    const __half* __restrict__ in, const uint2* __restrict__ wp,
    const float* __restrict__ bA, const float* __restrict__ bB2, const float* __restrict__ bC,
    const float* __restrict__ pr, void* __restrict__ outv)
{
    constexpr int P = MW * MT * 16;
    constexpr int PP = P + 2;
    constexpr int NKS = CIN / 16;
    constexpr int SEGS = 2 * NKS;
    constexpr int SLOTU2 = NKS * PP * 4;
    constexpr int WSEGS = 9 * NKS * NTOT * 2;

    extern __shared__ __align__(16) char smraw[];
    const uint2* w_u2 = (const uint2*)smraw + 4 * SLOTU2;
    const uint32_t a_u = smem_u32(smraw);
    const uint32_t w_addr = a_u + (uint32_t)(4 * SLOTU2 * 8);

    const int tid = threadIdx.x;
    const int lane = tid & 31;
    const int wid = tid >> 5;
    const int g = lane >> 2, tg = lane & 3;
    const int lrow = lane & 15, lhalf = lane >> 4;
    const int mbase = (wid % MW) * MT * 16;
    const int nbase = (wid / MW) * NT * 8;
    const int x0 = blockIdx.x * P;
    const int y0 = blockIdx.y * 8;
    const int b = blockIdx.z;

    const __half* inb = in + (size_t)b * HW * CIN;

    auto stage = [&](int yy) {
        const int slot = (yy + 4) & 3;
        const uint32_t sbase = a_u + (uint32_t)(slot * SLOTU2 * 8);
        const bool rok = ((unsigned)yy < HH);
        const __half* rowp = inb + (size_t)yy * WW * CIN;
        for (int i = tid; i < PP * SEGS; i += 256) {
            const int p = i / SEGS;
            const int s = i % SEGS;
            const int ks = s >> 1, h = s & 1;
            const int gx = x0 + p - 1;
            const uint32_t dst = sbase + (uint32_t)(ks * PP * 32) + psw(p, h);
            if (rok && (unsigned)gx < WW)
                CP_A16(dst, rowp + (size_t)gx * CIN + ks * 16 + h * 8);
            else
                STZ16(dst);
        }
    };

    for (int i = tid; i < WSEGS; i += 256)
        CP_A16(w_addr + (uint32_t)i * 16, (const char*)wp + (size_t)i * 16);
    if (GRP == 2) { stage(y0 - 1); stage(y0); stage(y0 + 1); stage(y0 + 2); }
    else          { stage(y0 - 1); stage(y0); stage(y0 + 1); }
    CP_COMMIT();

    __half* obH = (__half*)outv + (size_t)b * HW * NTOT;
    const float alpha = pr ? pr[0] : 0.f;
    const int pb0 = mbase + lrow;

    // epilogue for one output row from one acc set
    auto epi = [&](int y, float (*acc)[NT][4]) {
        #pragma unroll
        for (int mt = 0; mt < MT; mt++) {
            const int px = x0 + mbase + mt * 16 + g;
            #pragma unroll
            for (int nt = 0; nt < NT; nt++) {
                const int ch = nbase + nt * 8 + tg * 2;
                if (H3) {
                    if (ch < 12) {
                        const int st = ch >> 2, c4 = ch & 3;
                        const float* bp = (st == 0) ? bA : (st == 1 ? bB2 : bC);
                        const float bv0 = bp[c4], bv1 = bp[c4 + 1];
                        float* hb = (float*)outv + st * SST + (size_t)b * HW * 4;
                        float2 lo = make_float2(acc[mt][nt][0] + bv0, acc[mt][nt][1] + bv1);
                        float2 hi = make_float2(acc[mt][nt][2] + bv0, acc[mt][nt][3] + bv1);
                        *(float2*)(hb + ((size_t)y * WW + px) * 4 + c4) = lo;
                        *(float2*)(hb + ((size_t)y * WW + px + 8) * 4 + c4) = hi;
                    }
                } else {
                    const float bv0 = bA[ch], bv1 = bA[ch + 1];
                    float v0 = acc[mt][nt][0] + bv0;
                    float v1 = acc[mt][nt][1] + bv1;
                    float v2 = acc[mt][nt][2] + bv0;
                    float v3 = acc[mt][nt][3] + bv1;
                    if (v0 < 0.f) v0 *= alpha;
                    if (v1 < 0.f) v1 *= alpha;
                    if (v2 < 0.f) v2 *= alpha;
                    if (v3 < 0.f) v3 *= alpha;
                    *(uint32_t*)(obH + ((size_t)y * WW + px) * NTOT + ch) = pack_h2(v0, v1);
                    *(uint32_t*)(obH + ((size_t)y * WW + px + 8) * NTOT + ch) = pack_h2(v2, v3);
                }
            }
        }
    };

    if (GRP == 2) {
        // ---- row-pair mainloop: 4 iterations, 2 output rows each ----
        #pragma unroll 1
        for (int gi = 0; gi < 4; gi++) {
            const int y = y0 + 2 * gi;
            CP_WAIT0();
            __syncthreads();

            float acc[2][MT][NT][4];
            #pragma unroll
            for (int o = 0; o < 2; o++)
                #pragma unroll
                for (int mt = 0; mt < MT; mt++)
                    #pragma unroll
                    for (int nt = 0; nt < NT; nt++)
                        #pragma unroll
                        for (int e = 0; e < 4; e++) acc[o][mt][nt][e] = 0.f;

            #pragma unroll
            for (int rof = 0; rof < 4; rof++) {
                const int slot = (y + 3 + rof) & 3;   // input row y-1+rof
                #pragma unroll
                for (int dx = 0; dx < 3; dx++) {
                    #pragma unroll
                    for (int ks = 0; ks < NKS; ks++) {
                        const uint32_t kbase = a_u + (uint32_t)(((slot * NKS + ks) * PP) * 32);
                        uint32_t m[MT][4];
                        #pragma unroll
                        for (int mt = 0; mt < MT; mt++)
                            ldsm4(m[mt], kbase + psw(pb0 + mt * 16 + dx, lhalf));
                        #pragma unroll
                        for (int o = 0; o < 2; o++) {
                            const int dy = rof - o;
                            if (dy < 0 || dy > 2) continue;
                            const int tap = dy * 3 + dx;
                            #pragma unroll
                            for (int nt = 0; nt < NT; nt++) {
                                const uint2 qw = w_u2[((tap * NKS + ks) * NTOT + nbase + nt * 8 + g) * 4 + tg];
                                #pragma unroll
                                for (int mt = 0; mt < MT; mt++)
                                    mma16(acc[o][mt][nt], m[mt][0], m[mt][1], m[mt][2], m[mt][3],
                                          qw.x, qw.y);
                            }
                        }
                    }
                }
            }

            __syncthreads();   // all warps done reading rows y-1..y+2
            if (gi < 3) { stage(y + 3); stage(y + 4); CP_COMMIT(); }
            epi(y, acc[0]);
            epi(y + 1, acc[1]);
        }
    } else {
        // ---- original single-row mainloop ----
        #pragma unroll 1
        for (int yi = 0; yi < 8; yi++) {
            const int y = y0 + yi;
            CP_WAIT0();
            __syncthreads();
            if (yi < 7) { stage(y + 2); CP_COMMIT(); }

            float acc[MT][NT][4];
            #pragma unroll
            for (int mt = 0; mt < MT; mt++)
                #pragma unroll
                for (int nt = 0; nt < NT; nt++)
                    #pragma unroll
                    for (int e = 0; e < 4; e++) acc[mt][nt][e] = 0.f;

            #pragma unroll 1
            for (int tap = 0; tap < 9; tap++) {
                const int dy = tap / 3, dx = tap - dy * 3;
                const int slot = (y + dy + 3) & 3;
                #pragma unroll
                for (int ks = 0; ks < NKS; ks++) {
                    const uint32_t kbase = a_u + (uint32_t)(((slot * NKS + ks) * PP) * 32);
                    uint32_t m[MT][4];
                    #pragma unroll
                    for (int mt = 0; mt < MT; mt++)
                        ldsm4(m[mt], kbase + psw(pb0 + mt * 16 + dx, lhalf));
                    #pragma unroll
                    for (int nt = 0; nt < NT; nt++) {
                        const uint2 qw = w_u2[((tap * NKS + ks) * NTOT + nbase + nt * 8 + g) * 4 + tg];
                        #pragma unroll
                        for (int mt = 0; mt < MT; mt++)
                            mma16(acc[mt][nt], m[mt][0], m[mt][1], m[mt][2], m[mt][3], qw.x, qw.y);
                    }
                }
            }
            epi(y, acc);
        }
    }
}

// ================= conv1: 3->32, f32x2 FMA + LDS.128 weights =================
__global__ __launch_bounds__(256) void conv1_k(
    const float* __restrict__ x, const float* __restrict__ w,
    const float* __restrict__ bias, const float* __restrict__ pr,
    __half* __restrict__ out)
{
    __shared__ float s_in[3][10][34];
    __shared__ ulonglong2 s_w4[27][8];
    __shared__ float s_b[32];

    const int tid = threadIdx.x;
    const int tx = tid & 31, ty = tid >> 5;
    const int x0 = blockIdx.x * 32, y0 = blockIdx.y * 8;
    const int b = blockIdx.z;

    for (int i = tid; i < 216; i += 256) {
        const int t = i / 8, j = i % 8;
        const uint32_t a0 = __float_as_uint(w[(4 * j) * 27 + t]);
        const uint32_t a1 = __float_as_uint(w[(4 * j + 1) * 27 + t]);
        const uint32_t a2 = __float_as_uint(w[(4 * j + 2) * 27 + t]);
        const uint32_t a3 = __float_as_uint(w[(4 * j + 3) * 27 + t]);
        ulonglong2 e;
        e.x = ((unsigned long long)a1 << 32) | a0;
        e.y = ((unsigned long long)a3 << 32) | a2;
        s_w4[t][j] = e;
    }
    if (tid < 32) s_b[tid] = bias[tid];
    for (int i = tid; i < 1020; i += 256) {
        const int c = i / 340, r = i % 340;
        const int rr = r / 34, cc = r % 34;
        const int gy = y0 - 1 + rr, gx = x0 - 1 + cc;
        float v = 0.f;
        if ((unsigned)gy < HH && (unsigned)gx < WW)
            v = x[((size_t)(b * 3 + c)) * HW + (size_t)gy * WW + gx];
        s_in[c][rr][cc] = v;
    }
    __syncthreads();

    float vin[27];
    #pragma unroll
    for (int c = 0; c < 3; c++)
        #pragma unroll
        for (int dy = 0; dy < 3; dy++)
            #pragma unroll
            for (int dx = 0; dx < 3; dx++)
                vin[c * 9 + dy * 3 + dx] = s_in[c][ty + dy][tx + dx];

    unsigned long long acc2[16];
    #pragma unroll
    for (int j = 0; j < 16; j++) acc2[j] = 0ull;
    #pragma unroll
    for (int t = 0; t < 27; t++) {
        unsigned long long vv;
        asm("mov.b64 %0, {%1, %1};" : "=l"(vv) : "r"(__float_as_uint(vin[t])));
        #pragma unroll
        for (int j = 0; j < 8; j++) {
            const ulonglong2 ww = s_w4[t][j];
            fma2(acc2[2 * j], vv, ww.x);
            fma2(acc2[2 * j + 1], vv, ww.y);
        }
    }

    const float alpha = pr[0];
    uint32_t uu[16];
    #pragma unroll
    for (int j = 0; j < 16; j++) {
        uint32_t lo, hi;
        asm("mov.b64 {%0, %1}, %2;" : "=r"(lo), "=r"(hi) : "l"(acc2[j]));
        float v0 = __uint_as_float(lo) + s_b[2 * j];
        float v1 = __uint_as_float(hi) + s_b[2 * j + 1];
        if (v0 < 0.f) v0 *= alpha;
        if (v1 < 0.f) v1 *= alpha;
        uu[j] = pack_h2(v0, v1);
    }
    __half* dst = out + ((size_t)b * HW + (size_t)(y0 + ty) * WW + x0 + tx) * 32;
    #pragma unroll
    for (int q = 0; q < 4; q++)
        ((uint4*)dst)[q] = make_uint4(uu[4 * q], uu[4 * q + 1], uu[4 * q + 2], uu[4 * q + 3]);
}

// ================= GAP partials =================
__global__ __launch_bounds__(256) void gapp_k(const float* __restrict__ hp, float* __restrict__ part)
{
    __shared__ float red[8][12];
    const int b = blockIdx.x, seg = blockIdx.y;
    const int tid = threadIdx.x;
    float s[12];
    #pragma unroll
    for (int c = 0; c < 12; c++) s[c] = 0.f;
    #pragma unroll
    for (int st = 0; st < 3; st++) {
        const float4* base = (const float4*)(hp + st * SST + ((size_t)b * HW + (size_t)seg * (HW / 16)) * 4);
        for (int i = tid; i < HW / 16; i += 256) {
            const float4 q = base[i];
            s[st * 4 + 0] += q.x; s[st * 4 + 1] += q.y;
            s[st * 4 + 2] += q.z; s[st * 4 + 3] += q.w;
        }
    }
    #pragma unroll
    for (int k = 16; k > 0; k >>= 1)
        #pragma unroll
        for (int c = 0; c < 12; c++) s[c] += __shfl_xor_sync(0xffffffffu, s[c], k);
    if ((tid & 31) == 0)
        #pragma unroll
        for (int c = 0; c < 12; c++) red[tid >> 5][c] = s[c];
    __syncthreads();
    if (tid < 12) {
        float t = 0.f;
        #pragma unroll
        for (int wdx = 0; wdx < 8; wdx++) t += red[wdx][tid];
        part[((size_t)b * 16 + seg) * 12 + tid] = t;
    }
}

// ================= fused GAP-combine + SE =================
__global__ void gapse_k(const float* __restrict__ part,
                        const float* __restrict__ c1a, const float* __restrict__ c2a,
                        const float* __restrict__ c1b, const float* __restrict__ c2b,
                        const float* __restrict__ c1c, const float* __restrict__ c2c,
                        float* __restrict__ sout)
{
    __shared__ float gg[8][12];
    __shared__ float tt[8][12];
    const int t = threadIdx.x;
    const int b = t / 12, c = t % 12;
    const int st = c >> 2, c4 = c & 3;
    const float* c1 = (st == 0) ? c1a : (st == 1 ? c1b : c1c);
    const float* c2 = (st == 0) ? c2a : (st == 1 ? c2b : c2c);
    if (t < 96) {
        float s = 0.f;
        #pragma unroll
        for (int k = 0; k < 16; k++) s += part[((size_t)b * 16 + k) * 12 + c];
        gg[b][c] = s * (1.0f / HW);
    }
    __syncthreads();
    if (t < 96) {
        float v = 0.f;
        #pragma unroll
        for (int k = 0; k < 4; k++) v += c1[c4 * 4 + k] * gg[b][st * 4 + k];
        tt[b][c] = fmaxf(v, 0.f);
    }
    __syncthreads();
    if (t < 96) {
        float v = 0.f;
        #pragma unroll
        for (int k = 0; k < 4; k++) v += c2[c4 * 4 + k] * tt[b][st * 4 + k];
        sout[st * 32 + b * 4 + c4] = 1.f / (1.f + __expf(-v));
    }
}

// ================= fused blur + softmax + combine, 64x64 tiles =================
__global__ __launch_bounds__(256) void blurfuse_k(
    const float* __restrict__ src, const float* __restrict__ hp,
    const float* __restrict__ sv, float* __restrict__ out)
{
    extern __shared__ float bsm[];
    float (*s_src)[89] = (float(*)[89])bsm;
    float (*s_h5)[84]  = (float(*)[84])(bsm + 88 * 89);
    float (*s_h15)[64] = (float(*)[64])(bsm + 88 * 89 + 88 * 84);
    float (*s_h25)[64] = (float(*)[64])(bsm + 88 * 89 + 88 * 84 + 88 * 64);

    const int tx = threadIdx.x, ty = threadIdx.y;
    const int tid = ty * 64 + tx;
    const int x0 = blockIdx.x * 64, y0 = blockIdx.y * 64;
    const int z = blockIdx.z;
    const int c = z % 3, b = z / 3;
    const size_t cb = (size_t)(b * 3 + c) * HW;

    for (int i = tid; i < 88 * 88; i += 256) {
        const int r = i / 88, cc = i % 88;
        const int gy = y0 - 12 + r, gx = x0 - 12 + cc;
        float v = 0.f;
        if ((unsigned)gy < HH && (unsigned)gx < WW)
            v = src[cb + (size_t)gy * WW + gx];
        s_src[r][cc] = v;
    }
    __syncthreads();

    for (int i = tid; i < 88 * 84; i += 256) {
        const int r = i / 84, j = i % 84;
        s_h5[r][j] = s_src[r][j] + s_src[r][j + 1] + s_src[r][j + 2]
                   + s_src[r][j + 3] + s_src[r][j + 4];
    }
    __syncthreads();

    for (int i = tid; i < 88 * 64; i += 256) {
        const int r = i / 64, t = i % 64;
        const float h15 = s_h5[r][t + 5] + s_h5[r][t + 10] + s_h5[r][t + 15];
        s_h15[r][t] = h15;
        s_h25[r][t] = h15 + s_h5[r][t] + s_h5[r][t + 20];
    }
    __syncthreads();

    const int r0 = ty * 16 + 12;
    float v5 = 0.f, v15 = 0.f, v25 = 0.f;
    #pragma unroll
    for (int d = -2; d <= 2; d++) v5 += s_h5[r0 + d][tx + 10];
    #pragma unroll
    for (int d = -7; d <= 7; d++) v15 += s_h15[r0 + d][tx];
    #pragma unroll
    for (int d = -12; d <= 12; d++) v25 += s_h25[r0 + d][tx];

    const float s0 = sv[b * 4 + 0], s1 = sv[b * 4 + 1], s2 = sv[b * 4 + 2], s3 = sv[b * 4 + 3];
    const int x = x0 + tx;
    const float4* hppix = (const float4*)(hp + (size_t)b * HW * 4);

    #pragma unroll 1
    for (int j = 0; j < 16; j++) {
        const int y = y0 + ty * 16 + j;
        const int r = r0 + j;
        const float4 hv = hppix[(size_t)y * WW + x];
        float e0 = hv.x * s0, e1 = hv.y * s1, e2 = hv.z * s2, e3 = hv.w * s3;
        float m = fmaxf(fmaxf(e0, e1), fmaxf(e2, e3));
        float w0 = __expf(e0 - m), w1 = __expf(e1 - m), w2 = __expf(e2 - m), w3 = __expf(e3 - m);
        float inv = 1.f / (w0 + w1 + w2 + w3);
        float o = (w0 * inv) * s_src[r][tx + 12]
                + (w1 * inv) * (v5 * (1.f / 25.f))
                + (w2 * inv) * (v15 * (1.f / 225.f))
                + (w3 * inv) * (v25 * (1.f / 625.f));
        out[cb + (size_t)y * WW + x] = o;
        if (j < 15) {
            v5 += s_h5[r + 3][tx + 10] - s_h5[r - 2][tx + 10];
            v15 += s_h15[r + 8][tx] - s_h15[r - 7][tx];
            v25 += s_h25[r + 13][tx] - s_h25[r - 12][tx];
        }
    }
}

// ================= launch =================
extern "C" void kernel_launch(void* const* d_in, const int* in_sizes, int n_in,
                              void* d_out, int out_size)
{
    const float* x   = (const float*)d_in[0];
    const float* bw1 = (const float*)d_in[1];
    const float* bb1 = (const float*)d_in[2];
    const float* a1  = (const float*)d_in[3];
    const float* bw2 = (const float*)d_in[4];
    const float* bb2 = (const float*)d_in[5];
    const float* a2  = (const float*)d_in[6];
    const float* bw3 = (const float*)d_in[7];
    const float* bb3 = (const float*)d_in[8];
    const float* a3  = (const float*)d_in[9];
    const float* hw_[3]  = { (const float*)d_in[10], (const float*)d_in[14], (const float*)d_in[18] };
    const float* hb_[3]  = { (const float*)d_in[11], (const float*)d_in[15], (const float*)d_in[19] };
    const float* hc1_[3] = { (const float*)d_in[12], (const float*)d_in[16], (const float*)d_in[20] };
    const float* hc2_[3] = { (const float*)d_in[13], (const float*)d_in[17], (const float*)d_in[21] };

    float *B1, *B2, *P, *S, *TX, *TX2;
    uint2 *W2p, *W3p, *WHp;
    cudaGetSymbolAddress((void**)&B1, g_B1);
    cudaGetSymbolAddress((void**)&B2, g_B2);
    cudaGetSymbolAddress((void**)&P, g_P);
    cudaGetSymbolAddress((void**)&S, g_S);
    cudaGetSymbolAddress((void**)&TX, g_TX);
    cudaGetSymbolAddress((void**)&TX2, g_TX2);
    cudaGetSymbolAddress((void**)&W2p, g_W2);
    cudaGetSymbolAddress((void**)&W3p, g_W3);
    cudaGetSymbolAddress((void**)&WHp, g_WH);
    __half* B1h = (__half*)B1;
    __half* B2h = (__half*)B2;

    const int smem2 = 4 * 2 * 258 * 32 + 9 * 2 * 64 * 32;  // 102912
    const int smem3 = 4 * 4 * 130 * 32 + 9 * 4 * 32 * 32;  // 103424
    const int smemH = 4 * 2 * 258 * 32 + 9 * 2 * 16 * 32;  // 75264
    const int smemF = (88 * 89 + 88 * 84 + 2 * 88 * 64) * 4;  // 105952
    cudaFuncSetAttribute((const void*)mconv_k<32, 64, 4, 4, 4, false, 1>,
                         cudaFuncAttributeMaxDynamicSharedMemorySize, smem2);
    cudaFuncSetAttribute((const void*)mconv_k<64, 32, 4, 2, 2, false, 2>,
                         cudaFuncAttributeMaxDynamicSharedMemorySize, smem3);
    cudaFuncSetAttribute((const void*)mconv_k<32, 16, 8, 2, 2, true, 2>,
                         cudaFuncAttributeMaxDynamicSharedMemorySize, smemH);
    cudaFuncSetAttribute((const void*)blurfuse_k,
                         cudaFuncAttributeMaxDynamicSharedMemorySize, smemF);

    // ---- weight pre-transform ----
    wprep_k<<<(4608 + 4608 + 1152 + 255) / 256, 256>>>(bw2, bw3, hw_[0], hw_[1], hw_[2],
                                                       W2p, W3p, WHp);

    // ---- body ----
    conv1_k<<<dim3(16, 64, BB), 256>>>(x, bw1, bb1, a1, B1h);
    mconv_k<32, 64, 4, 4, 4, false, 1><<<dim3(2, 64, BB), 256, smem2>>>(
        B1h, W2p, bb2, nullptr, nullptr, a2, B2h);
    mconv_k<64, 32, 4, 2, 2, false, 2><<<dim3(4, 64, BB), 256, smem3>>>(
        B2h, W3p, bb3, nullptr, nullptr, a3, B1h);

    // ---- heads -> 3 packed stage buffers ----
    float* HP = B2;
    mconv_k<32, 16, 8, 2, 2, true, 2><<<dim3(2, 64, BB), 256, smemH>>>(
        B1h, WHp, hb_[0], hb_[1], hb_[2], nullptr, HP);
    gapp_k<<<dim3(BB, 16), 256>>>(HP, P);
    gapse_k<<<1, 96>>>(P, hc1_[0], hc2_[0], hc1_[1], hc2_[1], hc1_[2], hc2_[2], S);

    // ---- fused blur+softmax+combine (ping-pong) ----
    const dim3 fgrid(8, 8, BB * 3);
    const dim3 fblk(64, 4);
    blurfuse_k<<<fgrid, fblk, smemF>>>(x,   HP + 0 * SST, S + 0,  TX);
    blurfuse_k<<<fgrid, fblk, smemF>>>(TX,  HP + 1 * SST, S + 32, TX2);
    blurfuse_k<<<fgrid, fblk, smemF>>>(TX2, HP + 2 * SST, S + 64, (float*)d_out);
    (void)in_sizes; (void)n_in; (void)out_size;
}

// round 13
// speedup vs baseline: 1.2779x; 1.0360x over previous
#include <cuda_runtime.h>
#include <cuda_fp16.h>
#include <cstdint>
#include <cstddef>

#define HH 512
#define WW 512
#define BB 8
constexpr int HW = HH * WW;
constexpr size_t SST = (size_t)BB * HW * 4;   // floats per head-stage buffer

// ---------------- scratch ----------------
__device__ float g_B1[(size_t)BB * HW * 32 / 2];   // fp16 NHWC 32ch
__device__ float g_B2[(size_t)BB * HW * 64];       // fp16 64ch / 3x packed HP stage buffers
__device__ float g_P[BB * 16 * 12];
__device__ float g_S[3 * BB * 4];
__device__ float g_TX[(size_t)BB * 3 * HW];
__device__ float g_TX2[(size_t)BB * 3 * HW];
__device__ uint2 g_W2[9 * 2 * 64 * 4];
__device__ uint2 g_W3[9 * 4 * 32 * 4];
__device__ uint2 g_WH[9 * 2 * 16 * 4];

// ---------------- helpers ----------------
__device__ __forceinline__ uint32_t smem_u32(const void* p) {
    uint32_t r;
    asm("{ .reg .u64 t; cvta.to.shared.u64 t, %1; cvt.u32.u64 %0, t; }" : "=r"(r) : "l"(p));
    return r;
}
__device__ __forceinline__ uint32_t pack_h2(float a, float b) {
    __half2 h = __floats2half2_rn(a, b);
    return *(uint32_t*)&h;
}
__device__ __forceinline__ void mma16(float* d, uint32_t a0, uint32_t a1, uint32_t a2,
                                      uint32_t a3, uint32_t b0, uint32_t b1) {
    asm volatile(
        "mma.sync.aligned.m16n8k16.row.col.f32.f16.f16.f32 "
        "{%0,%1,%2,%3}, {%4,%5,%6,%7}, {%8,%9}, {%0,%1,%2,%3};"
        : "+f"(d[0]), "+f"(d[1]), "+f"(d[2]), "+f"(d[3])
        : "r"(a0), "r"(a1), "r"(a2), "r"(a3), "r"(b0), "r"(b1));
}
__device__ __forceinline__ void ldsm4(uint32_t* r, uint32_t addr) {
    asm volatile("ldmatrix.sync.aligned.m8n8.x4.shared.b16 {%0,%1,%2,%3}, [%4];"
                 : "=r"(r[0]), "=r"(r[1]), "=r"(r[2]), "=r"(r[3]) : "r"(addr));
}
__device__ __forceinline__ void fma2(unsigned long long& d, unsigned long long a,
                                     unsigned long long b) {
    asm("fma.rn.f32x2 %0, %1, %2, %0;" : "+l"(d) : "l"(a), "l"(b));
}
#define CP_A16(dst, src) asm volatile("cp.async.ca.shared.global [%0], [%1], 16;" :: "r"(dst), "l"(src) : "memory")
#define CP_COMMIT()      asm volatile("cp.async.commit_group;" ::: "memory")
#define CP_WAIT0()       asm volatile("cp.async.wait_group 0;" ::: "memory")
#define STZ16(dst)       asm volatile("st.shared.v4.b32 [%0], {%1,%1,%1,%1};" :: "r"(dst), "r"(0u) : "memory")

// pixel-half swizzle: physical 16B-half of pixel p, logical half h (bank-conflict-free ldmatrix)
__device__ __forceinline__ uint32_t psw(int p, int h) {
    return (uint32_t)(p * 32 + ((h ^ ((p >> 2) & 1)) << 4));
}

// ================= fused weight pre-transform =================
__device__ void wprep_one(const float* wA, const float* wB2, const float* wC,
                          int CIN, int NTOT, int H3, uint2* out, int i)
{
    const int NKS = CIN / 16;
    const int tap = i / (NKS * NTOT * 4);
    int r = i % (NKS * NTOT * 4);
    const int ks = r / (NTOT * 4);
    r %= NTOT * 4;
    const int n = r >> 2, t4 = r & 3;
    float v0 = 0.f, v1 = 0.f, v2 = 0.f, v3 = 0.f;
    const int cb = ks * 16 + t4 * 2;
    if (H3) {
        if (n < 12) {
            const float* wp = (n < 4) ? wA : (n < 8 ? wB2 : wC);
            const size_t nb = (size_t)(n & 3) * CIN;
            v0 = wp[(nb + cb) * 9 + tap];
            v1 = wp[(nb + cb + 1) * 9 + tap];
            v2 = wp[(nb + cb + 8) * 9 + tap];
            v3 = wp[(nb + cb + 9) * 9 + tap];
        }
    } else {
        const size_t nb = (size_t)n * CIN;
        v0 = wA[(nb + cb) * 9 + tap];
        v1 = wA[(nb + cb + 1) * 9 + tap];
        v2 = wA[(nb + cb + 8) * 9 + tap];
        v3 = wA[(nb + cb + 9) * 9 + tap];
    }
    uint2 e;
    e.x = pack_h2(v0, v1);
    e.y = pack_h2(v2, v3);
    out[i] = e;
}

__global__ void wprep_k(const float* __restrict__ w2, const float* __restrict__ w3,
                        const float* __restrict__ hA, const float* __restrict__ hB,
                        const float* __restrict__ hC,
                        uint2* __restrict__ o2, uint2* __restrict__ o3, uint2* __restrict__ oH)
{
    constexpr int T2 = 9 * 2 * 64 * 4;
    constexpr int T3 = 9 * 4 * 32 * 4;
    constexpr int TH = 9 * 2 * 16 * 4;
    int i = blockIdx.x * 256 + threadIdx.x;
    if (i < T2) { wprep_one(w2, nullptr, nullptr, 32, 64, 0, o2, i); return; }
    i -= T2;
    if (i < T3) { wprep_one(w3, nullptr, nullptr, 64, 32, 0, o3, i); return; }
    i -= T3;
    if (i < TH) { wprep_one(hA, hB, hC, 32, 16, 1, oH, i); }
}

// ================= fp16 m16n8k16 3x3 conv (swizzled ldmatrix, optional row-pairing) =================
template<int CIN, int NTOT, int MW, int MT, int NT, bool H3, int GRP>
__global__ __launch_bounds__(256, 2) void mconv_k(
    const __half* __restrict__ in, const uint2* __restrict__ wp,
    const float* __restrict__ bA, const float* __restrict__ bB2, const float* __restrict__ bC,
    const float* __restrict__ pr, void* __restrict__ outv)
{
    constexpr int P = MW * MT * 16;
    constexpr int PP = P + 2;
    constexpr int NKS = CIN / 16;
    constexpr int SEGS = 2 * NKS;
    constexpr int SLOTU2 = NKS * PP * 4;
    constexpr int WSEGS = 9 * NKS * NTOT * 2;

    extern __shared__ __align__(16) char smraw[];
    const uint2* w_u2 = (const uint2*)smraw + 4 * SLOTU2;
    const uint32_t a_u = smem_u32(smraw);
    const uint32_t w_addr = a_u + (uint32_t)(4 * SLOTU2 * 8);

    const int tid = threadIdx.x;
    const int lane = tid & 31;
    const int wid = tid >> 5;
    const int g = lane >> 2, tg = lane & 3;
    const int lrow = lane & 15, lhalf = lane >> 4;
    const int mbase = (wid % MW) * MT * 16;
    const int nbase = (wid / MW) * NT * 8;
    const int x0 = blockIdx.x * P;
    const int y0 = blockIdx.y * 8;
    const int b = blockIdx.z;

    const __half* inb = in + (size_t)b * HW * CIN;

    auto stage = [&](int yy) {
        const int slot = (yy + 4) & 3;
        const uint32_t sbase = a_u + (uint32_t)(slot * SLOTU2 * 8);
        const bool rok = ((unsigned)yy < HH);
        const __half* rowp = inb + (size_t)yy * WW * CIN;
        for (int i = tid; i < PP * SEGS; i += 256) {
            const int p = i / SEGS;
            const int s = i % SEGS;
            const int ks = s >> 1, h = s & 1;
            const int gx = x0 + p - 1;
            const uint32_t dst = sbase + (uint32_t)(ks * PP * 32) + psw(p, h);
            if (rok && (unsigned)gx < WW)
                CP_A16(dst, rowp + (size_t)gx * CIN + ks * 16 + h * 8);
            else
                STZ16(dst);
        }
    };

    for (int i = tid; i < WSEGS; i += 256)
        CP_A16(w_addr + (uint32_t)i * 16, (const char*)wp + (size_t)i * 16);
    if (GRP == 2) { stage(y0 - 1); stage(y0); stage(y0 + 1); stage(y0 + 2); }
    else          { stage(y0 - 1); stage(y0); stage(y0 + 1); }
    CP_COMMIT();

    __half* obH = (__half*)outv + (size_t)b * HW * NTOT;
    const float alpha = pr ? pr[0] : 0.f;
    const int pb0 = mbase + lrow;

    // epilogue for one output row from one acc set
    auto epi = [&](int y, float (*acc)[NT][4]) {
        #pragma unroll
        for (int mt = 0; mt < MT; mt++) {
            const int px = x0 + mbase + mt * 16 + g;
            #pragma unroll
            for (int nt = 0; nt < NT; nt++) {
                const int ch = nbase + nt * 8 + tg * 2;
                if (H3) {
                    if (ch < 12) {
                        const int st = ch >> 2, c4 = ch & 3;
                        const float* bp = (st == 0) ? bA : (st == 1 ? bB2 : bC);
                        const float bv0 = bp[c4], bv1 = bp[c4 + 1];
                        float* hb = (float*)outv + st * SST + (size_t)b * HW * 4;
                        float2 lo = make_float2(acc[mt][nt][0] + bv0, acc[mt][nt][1] + bv1);
                        float2 hi = make_float2(acc[mt][nt][2] + bv0, acc[mt][nt][3] + bv1);
                        *(float2*)(hb + ((size_t)y * WW + px) * 4 + c4) = lo;
                        *(float2*)(hb + ((size_t)y * WW + px + 8) * 4 + c4) = hi;
                    }
                } else {
                    const float bv0 = bA[ch], bv1 = bA[ch + 1];
                    float v0 = acc[mt][nt][0] + bv0;
                    float v1 = acc[mt][nt][1] + bv1;
                    float v2 = acc[mt][nt][2] + bv0;
                    float v3 = acc[mt][nt][3] + bv1;
                    if (v0 < 0.f) v0 *= alpha;
                    if (v1 < 0.f) v1 *= alpha;
                    if (v2 < 0.f) v2 *= alpha;
                    if (v3 < 0.f) v3 *= alpha;
                    *(uint32_t*)(obH + ((size_t)y * WW + px) * NTOT + ch) = pack_h2(v0, v1);
                    *(uint32_t*)(obH + ((size_t)y * WW + px + 8) * NTOT + ch) = pack_h2(v2, v3);
                }
            }
        }
    };

    if (GRP == 2) {
        // ---- row-pair mainloop: 4 iterations, 2 output rows each ----
        #pragma unroll 1
        for (int gi = 0; gi < 4; gi++) {
            const int y = y0 + 2 * gi;
            CP_WAIT0();
            __syncthreads();

            float acc[2][MT][NT][4];
            #pragma unroll
            for (int o = 0; o < 2; o++)
                #pragma unroll
                for (int mt = 0; mt < MT; mt++)
                    #pragma unroll
                    for (int nt = 0; nt < NT; nt++)
                        #pragma unroll
                        for (int e = 0; e < 4; e++) acc[o][mt][nt][e] = 0.f;

            #pragma unroll
            for (int rof = 0; rof < 4; rof++) {
                const int slot = (y + 3 + rof) & 3;   // input row y-1+rof
                #pragma unroll
                for (int dx = 0; dx < 3; dx++) {
                    #pragma unroll
                    for (int ks = 0; ks < NKS; ks++) {
                        const uint32_t kbase = a_u + (uint32_t)(((slot * NKS + ks) * PP) * 32);
                        uint32_t m[MT][4];
                        #pragma unroll
                        for (int mt = 0; mt < MT; mt++)
                            ldsm4(m[mt], kbase + psw(pb0 + mt * 16 + dx, lhalf));
                        #pragma unroll
                        for (int o = 0; o < 2; o++) {
                            const int dy = rof - o;
                            if (dy < 0 || dy > 2) continue;
                            const int tap = dy * 3 + dx;
                            #pragma unroll
                            for (int nt = 0; nt < NT; nt++) {
                                const uint2 qw = w_u2[((tap * NKS + ks) * NTOT + nbase + nt * 8 + g) * 4 + tg];
                                #pragma unroll
                                for (int mt = 0; mt < MT; mt++)
                                    mma16(acc[o][mt][nt], m[mt][0], m[mt][1], m[mt][2], m[mt][3],
                                          qw.x, qw.y);
                            }
                        }
                    }
                }
            }

            __syncthreads();   // all warps done reading rows y-1..y+2
            if (gi < 3) { stage(y + 3); stage(y + 4); CP_COMMIT(); }
            epi(y, acc[0]);
            epi(y + 1, acc[1]);
        }
    } else {
        // ---- single-row mainloop ----
        #pragma unroll 1
        for (int yi = 0; yi < 8; yi++) {
            const int y = y0 + yi;
            CP_WAIT0();
            __syncthreads();
            if (yi < 7) { stage(y + 2); CP_COMMIT(); }

            float acc[MT][NT][4];
            #pragma unroll
            for (int mt = 0; mt < MT; mt++)
                #pragma unroll
                for (int nt = 0; nt < NT; nt++)
                    #pragma unroll
                    for (int e = 0; e < 4; e++) acc[mt][nt][e] = 0.f;

            #pragma unroll 1
            for (int tap = 0; tap < 9; tap++) {
                const int dy = tap / 3, dx = tap - dy * 3;
                const int slot = (y + dy + 3) & 3;
                #pragma unroll
                for (int ks = 0; ks < NKS; ks++) {
                    const uint32_t kbase = a_u + (uint32_t)(((slot * NKS + ks) * PP) * 32);
                    uint32_t m[MT][4];
                    #pragma unroll
                    for (int mt = 0; mt < MT; mt++)
                        ldsm4(m[mt], kbase + psw(pb0 + mt * 16 + dx, lhalf));
                    #pragma unroll
                    for (int nt = 0; nt < NT; nt++) {
                        const uint2 qw = w_u2[((tap * NKS + ks) * NTOT + nbase + nt * 8 + g) * 4 + tg];
                        #pragma unroll
                        for (int mt = 0; mt < MT; mt++)
                            mma16(acc[mt][nt], m[mt][0], m[mt][1], m[mt][2], m[mt][3], qw.x, qw.y);
                    }
                }
            }
            epi(y, acc);
        }
    }
}

// ================= conv1: 3->32, f32x2 FMA + LDS.128 weights =================
__global__ __launch_bounds__(256) void conv1_k(
    const float* __restrict__ x, const float* __restrict__ w,
    const float* __restrict__ bias, const float* __restrict__ pr,
    __half* __restrict__ out)
{
    __shared__ float s_in[3][10][34];
    __shared__ ulonglong2 s_w4[27][8];
    __shared__ float s_b[32];

    const int tid = threadIdx.x;
    const int tx = tid & 31, ty = tid >> 5;
    const int x0 = blockIdx.x * 32, y0 = blockIdx.y * 8;
    const int b = blockIdx.z;

    for (int i = tid; i < 216; i += 256) {
        const int t = i / 8, j = i % 8;
        const uint32_t a0 = __float_as_uint(w[(4 * j) * 27 + t]);
        const uint32_t a1 = __float_as_uint(w[(4 * j + 1) * 27 + t]);
        const uint32_t a2 = __float_as_uint(w[(4 * j + 2) * 27 + t]);
        const uint32_t a3 = __float_as_uint(w[(4 * j + 3) * 27 + t]);
        ulonglong2 e;
        e.x = ((unsigned long long)a1 << 32) | a0;
        e.y = ((unsigned long long)a3 << 32) | a2;
        s_w4[t][j] = e;
    }
    if (tid < 32) s_b[tid] = bias[tid];
    for (int i = tid; i < 1020; i += 256) {
        const int c = i / 340, r = i % 340;
        const int rr = r / 34, cc = r % 34;
        const int gy = y0 - 1 + rr, gx = x0 - 1 + cc;
        float v = 0.f;
        if ((unsigned)gy < HH && (unsigned)gx < WW)
            v = x[((size_t)(b * 3 + c)) * HW + (size_t)gy * WW + gx];
        s_in[c][rr][cc] = v;
    }
    __syncthreads();

    float vin[27];
    #pragma unroll
    for (int c = 0; c < 3; c++)
        #pragma unroll
        for (int dy = 0; dy < 3; dy++)
            #pragma unroll
            for (int dx = 0; dx < 3; dx++)
                vin[c * 9 + dy * 3 + dx] = s_in[c][ty + dy][tx + dx];

    unsigned long long acc2[16];
    #pragma unroll
    for (int j = 0; j < 16; j++) acc2[j] = 0ull;
    #pragma unroll
    for (int t = 0; t < 27; t++) {
        unsigned long long vv;
        asm("mov.b64 %0, {%1, %1};" : "=l"(vv) : "r"(__float_as_uint(vin[t])));
        #pragma unroll
        for (int j = 0; j < 8; j++) {
            const ulonglong2 ww = s_w4[t][j];
            fma2(acc2[2 * j], vv, ww.x);
            fma2(acc2[2 * j + 1], vv, ww.y);
        }
    }

    const float alpha = pr[0];
    uint32_t uu[16];
    #pragma unroll
    for (int j = 0; j < 16; j++) {
        uint32_t lo, hi;
        asm("mov.b64 {%0, %1}, %2;" : "=r"(lo), "=r"(hi) : "l"(acc2[j]));
        float v0 = __uint_as_float(lo) + s_b[2 * j];
        float v1 = __uint_as_float(hi) + s_b[2 * j + 1];
        if (v0 < 0.f) v0 *= alpha;
        if (v1 < 0.f) v1 *= alpha;
        uu[j] = pack_h2(v0, v1);
    }
    __half* dst = out + ((size_t)b * HW + (size_t)(y0 + ty) * WW + x0 + tx) * 32;
    #pragma unroll
    for (int q = 0; q < 4; q++)
        ((uint4*)dst)[q] = make_uint4(uu[4 * q], uu[4 * q + 1], uu[4 * q + 2], uu[4 * q + 3]);
}

// ================= GAP partials =================
__global__ __launch_bounds__(256) void gapp_k(const float* __restrict__ hp, float* __restrict__ part)
{
    __shared__ float red[8][12];
    const int b = blockIdx.x, seg = blockIdx.y;
    const int tid = threadIdx.x;
    float s[12];
    #pragma unroll
    for (int c = 0; c < 12; c++) s[c] = 0.f;
    #pragma unroll
    for (int st = 0; st < 3; st++) {
        const float4* base = (const float4*)(hp + st * SST + ((size_t)b * HW + (size_t)seg * (HW / 16)) * 4);
        for (int i = tid; i < HW / 16; i += 256) {
            const float4 q = base[i];
            s[st * 4 + 0] += q.x; s[st * 4 + 1] += q.y;
            s[st * 4 + 2] += q.z; s[st * 4 + 3] += q.w;
        }
    }
    #pragma unroll
    for (int k = 16; k > 0; k >>= 1)
        #pragma unroll
        for (int c = 0; c < 12; c++) s[c] += __shfl_xor_sync(0xffffffffu, s[c], k);
    if ((tid & 31) == 0)
        #pragma unroll
        for (int c = 0; c < 12; c++) red[tid >> 5][c] = s[c];
    __syncthreads();
    if (tid < 12) {
        float t = 0.f;
        #pragma unroll
        for (int wdx = 0; wdx < 8; wdx++) t += red[wdx][tid];
        part[((size_t)b * 16 + seg) * 12 + tid] = t;
    }
}

// ================= fused GAP-combine + SE =================
__global__ void gapse_k(const float* __restrict__ part,
                        const float* __restrict__ c1a, const float* __restrict__ c2a,
                        const float* __restrict__ c1b, const float* __restrict__ c2b,
                        const float* __restrict__ c1c, const float* __restrict__ c2c,
                        float* __restrict__ sout)
{
    __shared__ float gg[8][12];
    __shared__ float tt[8][12];
    const int t = threadIdx.x;
    const int b = t / 12, c = t % 12;
    const int st = c >> 2, c4 = c & 3;
    const float* c1 = (st == 0) ? c1a : (st == 1 ? c1b : c1c);
    const float* c2 = (st == 0) ? c2a : (st == 1 ? c2b : c2c);
    if (t < 96) {
        float s = 0.f;
        #pragma unroll
        for (int k = 0; k < 16; k++) s += part[((size_t)b * 16 + k) * 12 + c];
        gg[b][c] = s * (1.0f / HW);
    }
    __syncthreads();
    if (t < 96) {
        float v = 0.f;
        #pragma unroll
        for (int k = 0; k < 4; k++) v += c1[c4 * 4 + k] * gg[b][st * 4 + k];
        tt[b][c] = fmaxf(v, 0.f);
    }
    __syncthreads();
    if (t < 96) {
        float v = 0.f;
        #pragma unroll
        for (int k = 0; k < 4; k++) v += c2[c4 * 4 + k] * tt[b][st * 4 + k];
        sout[st * 32 + b * 4 + c4] = 1.f / (1.f + __expf(-v));
    }
}

// ================= fused blur + softmax + combine, 64x64 tiles =================
__global__ __launch_bounds__(256) void blurfuse_k(
    const float* __restrict__ src, const float* __restrict__ hp,
    const float* __restrict__ sv, float* __restrict__ out)
{
    extern __shared__ float bsm[];
    float (*s_src)[89] = (float(*)[89])bsm;
    float (*s_h5)[84]  = (float(*)[84])(bsm + 88 * 89);
    float (*s_h15)[64] = (float(*)[64])(bsm + 88 * 89 + 88 * 84);
    float (*s_h25)[64] = (float(*)[64])(bsm + 88 * 89 + 88 * 84 + 88 * 64);

    const int tx = threadIdx.x, ty = threadIdx.y;
    const int tid = ty * 64 + tx;
    const int x0 = blockIdx.x * 64, y0 = blockIdx.y * 64;
    const int z = blockIdx.z;
    const int c = z % 3, b = z / 3;
    const size_t cb = (size_t)(b * 3 + c) * HW;

    for (int i = tid; i < 88 * 88; i += 256) {
        const int r = i / 88, cc = i % 88;
        const int gy = y0 - 12 + r, gx = x0 - 12 + cc;
        float v = 0.f;
        if ((unsigned)gy < HH && (unsigned)gx < WW)
            v = src[cb + (size_t)gy * WW + gx];
        s_src[r][cc] = v;
    }
    __syncthreads();

    for (int i = tid; i < 88 * 84; i += 256) {
        const int r = i / 84, j = i % 84;
        s_h5[r][j] = s_src[r][j] + s_src[r][j + 1] + s_src[r][j + 2]
                   + s_src[r][j + 3] + s_src[r][j + 4];
    }
    __syncthreads();

    for (int i = tid; i < 88 * 64; i += 256) {
        const int r = i / 64, t = i % 64;
        const float h15 = s_h5[r][t + 5] + s_h5[r][t + 10] + s_h5[r][t + 15];
        s_h15[r][t] = h15;
        s_h25[r][t] = h15 + s_h5[r][t] + s_h5[r][t + 20];
    }
    __syncthreads();

    const int r0 = ty * 16 + 12;
    float v5 = 0.f, v15 = 0.f, v25 = 0.f;
    #pragma unroll
    for (int d = -2; d <= 2; d++) v5 += s_h5[r0 + d][tx + 10];
    #pragma unroll
    for (int d = -7; d <= 7; d++) v15 += s_h15[r0 + d][tx];
    #pragma unroll
    for (int d = -12; d <= 12; d++) v25 += s_h25[r0 + d][tx];

    const float s0 = sv[b * 4 + 0], s1 = sv[b * 4 + 1], s2 = sv[b * 4 + 2], s3 = sv[b * 4 + 3];
    const int x = x0 + tx;
    const float4* hppix = (const float4*)(hp + (size_t)b * HW * 4);

    #pragma unroll 1
    for (int j = 0; j < 16; j++) {
        const int y = y0 + ty * 16 + j;
        const int r = r0 + j;
        const float4 hv = hppix[(size_t)y * WW + x];
        float e0 = hv.x * s0, e1 = hv.y * s1, e2 = hv.z * s2, e3 = hv.w * s3;
        float m = fmaxf(fmaxf(e0, e1), fmaxf(e2, e3));
        float w0 = __expf(e0 - m), w1 = __expf(e1 - m), w2 = __expf(e2 - m), w3 = __expf(e3 - m);
        float inv = 1.f / (w0 + w1 + w2 + w3);
        float o = (w0 * inv) * s_src[r][tx + 12]
                + (w1 * inv) * (v5 * (1.f / 25.f))
                + (w2 * inv) * (v15 * (1.f / 225.f))
                + (w3 * inv) * (v25 * (1.f / 625.f));
        out[cb + (size_t)y * WW + x] = o;
        if (j < 15) {
            v5 += s_h5[r + 3][tx + 10] - s_h5[r - 2][tx + 10];
            v15 += s_h15[r + 8][tx] - s_h15[r - 7][tx];
            v25 += s_h25[r + 13][tx] - s_h25[r - 12][tx];
        }
    }
}

// ================= launch =================
extern "C" void kernel_launch(void* const* d_in, const int* in_sizes, int n_in,
                              void* d_out, int out_size)
{
    const float* x   = (const float*)d_in[0];
    const float* bw1 = (const float*)d_in[1];
    const float* bb1 = (const float*)d_in[2];
    const float* a1  = (const float*)d_in[3];
    const float* bw2 = (const float*)d_in[4];
    const float* bb2 = (const float*)d_in[5];
    const float* a2  = (const float*)d_in[6];
    const float* bw3 = (const float*)d_in[7];
    const float* bb3 = (const float*)d_in[8];
    const float* a3  = (const float*)d_in[9];
    const float* hw_[3]  = { (const float*)d_in[10], (const float*)d_in[14], (const float*)d_in[18] };
    const float* hb_[3]  = { (const float*)d_in[11], (const float*)d_in[15], (const float*)d_in[19] };
    const float* hc1_[3] = { (const float*)d_in[12], (const float*)d_in[16], (const float*)d_in[20] };
    const float* hc2_[3] = { (const float*)d_in[13], (const float*)d_in[17], (const float*)d_in[21] };

    float *B1, *B2, *P, *S, *TX, *TX2;
    uint2 *W2p, *W3p, *WHp;
    cudaGetSymbolAddress((void**)&B1, g_B1);
    cudaGetSymbolAddress((void**)&B2, g_B2);
    cudaGetSymbolAddress((void**)&P, g_P);
    cudaGetSymbolAddress((void**)&S, g_S);
    cudaGetSymbolAddress((void**)&TX, g_TX);
    cudaGetSymbolAddress((void**)&TX2, g_TX2);
    cudaGetSymbolAddress((void**)&W2p, g_W2);
    cudaGetSymbolAddress((void**)&W3p, g_W3);
    cudaGetSymbolAddress((void**)&WHp, g_WH);
    __half* B1h = (__half*)B1;
    __half* B2h = (__half*)B2;

    const int smem2 = 4 * 2 * 258 * 32 + 9 * 2 * 64 * 32;  // 102912
    const int smem3 = 4 * 4 * 130 * 32 + 9 * 4 * 32 * 32;  // 103424
    const int smemH = 4 * 2 * 258 * 32 + 9 * 2 * 16 * 32;  // 75264
    const int smemF = (88 * 89 + 88 * 84 + 2 * 88 * 64) * 4;  // 105952
    cudaFuncSetAttribute((const void*)mconv_k<32, 64, 4, 4, 4, false, 1>,
                         cudaFuncAttributeMaxDynamicSharedMemorySize, smem2);
    cudaFuncSetAttribute((const void*)mconv_k<64, 32, 4, 2, 2, false, 2>,
                         cudaFuncAttributeMaxDynamicSharedMemorySize, smem3);
    cudaFuncSetAttribute((const void*)mconv_k<32, 16, 8, 2, 2, true, 2>,
                         cudaFuncAttributeMaxDynamicSharedMemorySize, smemH);
    cudaFuncSetAttribute((const void*)blurfuse_k,
                         cudaFuncAttributeMaxDynamicSharedMemorySize, smemF);

    // ---- weight pre-transform ----
    wprep_k<<<(4608 + 4608 + 1152 + 255) / 256, 256>>>(bw2, bw3, hw_[0], hw_[1], hw_[2],
                                                       W2p, W3p, WHp);

    // ---- body ----
    conv1_k<<<dim3(16, 64, BB), 256>>>(x, bw1, bb1, a1, B1h);
    mconv_k<32, 64, 4, 4, 4, false, 1><<<dim3(2, 64, BB), 256, smem2>>>(
        B1h, W2p, bb2, nullptr, nullptr, a2, B2h);
    mconv_k<64, 32, 4, 2, 2, false, 2><<<dim3(4, 64, BB), 256, smem3>>>(
        B2h, W3p, bb3, nullptr, nullptr, a3, B1h);

    // ---- heads -> 3 packed stage buffers ----
    float* HP = B2;
    mconv_k<32, 16, 8, 2, 2, true, 2><<<dim3(2, 64, BB), 256, smemH>>>(
        B1h, WHp, hb_[0], hb_[1], hb_[2], nullptr, HP);
    gapp_k<<<dim3(BB, 16), 256>>>(HP, P);
    gapse_k<<<1, 96>>>(P, hc1_[0], hc2_[0], hc1_[1], hc2_[1], hc1_[2], hc2_[2], S);

    // ---- fused blur+softmax+combine (ping-pong) ----
    const dim3 fgrid(8, 8, BB * 3);
    const dim3 fblk(64, 4);
    blurfuse_k<<<fgrid, fblk, smemF>>>(x,   HP + 0 * SST, S + 0,  TX);
    blurfuse_k<<<fgrid, fblk, smemF>>>(TX,  HP + 1 * SST, S + 32, TX2);
    blurfuse_k<<<fgrid, fblk, smemF>>>(TX2, HP + 2 * SST, S + 64, (float*)d_out);
    (void)in_sizes; (void)n_in; (void)out_size;
}

// round 14
// speedup vs baseline: 1.3232x; 1.0354x over previous
#include <cuda_runtime.h>
#include <cuda_fp16.h>
#include <cstdint>
#include <cstddef>

#define HH 512
#define WW 512
#define BB 8
constexpr int HW = HH * WW;
constexpr size_t SST = (size_t)BB * HW * 4;   // floats per head-stage buffer

// ---------------- scratch ----------------
__device__ float g_B1[(size_t)BB * HW * 32 / 2];   // fp16 NHWC 32ch
__device__ float g_B2[(size_t)BB * HW * 64];       // fp16 64ch / 3x packed HP stage buffers
__device__ float g_P[BB * 128 * 12];               // per-block GAP partials
__device__ float g_S[3 * BB * 4];
__device__ float g_TX[(size_t)BB * 3 * HW];
__device__ float g_TX2[(size_t)BB * 3 * HW];
__device__ uint2 g_W2[9 * 2 * 64 * 4];
__device__ uint2 g_W3[9 * 4 * 32 * 4];
__device__ uint2 g_WH[9 * 2 * 16 * 4];

// ---------------- helpers ----------------
__device__ __forceinline__ uint32_t smem_u32(const void* p) {
    uint32_t r;
    asm("{ .reg .u64 t; cvta.to.shared.u64 t, %1; cvt.u32.u64 %0, t; }" : "=r"(r) : "l"(p));
    return r;
}
__device__ __forceinline__ uint32_t pack_h2(float a, float b) {
    __half2 h = __floats2half2_rn(a, b);
    return *(uint32_t*)&h;
}
__device__ __forceinline__ void mma16(float* d, uint32_t a0, uint32_t a1, uint32_t a2,
                                      uint32_t a3, uint32_t b0, uint32_t b1) {
    asm volatile(
        "mma.sync.aligned.m16n8k16.row.col.f32.f16.f16.f32 "
        "{%0,%1,%2,%3}, {%4,%5,%6,%7}, {%8,%9}, {%0,%1,%2,%3};"
        : "+f"(d[0]), "+f"(d[1]), "+f"(d[2]), "+f"(d[3])
        : "r"(a0), "r"(a1), "r"(a2), "r"(a3), "r"(b0), "r"(b1));
}
__device__ __forceinline__ void ldsm4(uint32_t* r, uint32_t addr) {
    asm volatile("ldmatrix.sync.aligned.m8n8.x4.shared.b16 {%0,%1,%2,%3}, [%4];"
                 : "=r"(r[0]), "=r"(r[1]), "=r"(r[2]), "=r"(r[3]) : "r"(addr));
}
__device__ __forceinline__ void fma2(unsigned long long& d, unsigned long long a,
                                     unsigned long long b) {
    asm("fma.rn.f32x2 %0, %1, %2, %0;" : "+l"(d) : "l"(a), "l"(b));
}
#define CP_A16(dst, src) asm volatile("cp.async.ca.shared.global [%0], [%1], 16;" :: "r"(dst), "l"(src) : "memory")
#define CP_COMMIT()      asm volatile("cp.async.commit_group;" ::: "memory")
#define CP_WAIT0()       asm volatile("cp.async.wait_group 0;" ::: "memory")
#define STZ16(dst)       asm volatile("st.shared.v4.b32 [%0], {%1,%1,%1,%1};" :: "r"(dst), "r"(0u) : "memory")

// pixel-half swizzle: conflict-free ldmatrix
__device__ __forceinline__ uint32_t psw(int p, int h) {
    return (uint32_t)(p * 32 + ((h ^ ((p >> 2) & 1)) << 4));
}

// ================= fused weight pre-transform =================
__device__ void wprep_one(const float* wA, const float* wB2, const float* wC,
                          int CIN, int NTOT, int H3, uint2* out, int i)
{
    const int NKS = CIN / 16;
    const int tap = i / (NKS * NTOT * 4);
    int r = i % (NKS * NTOT * 4);
    const int ks = r / (NTOT * 4);
    r %= NTOT * 4;
    const int n = r >> 2, t4 = r & 3;
    float v0 = 0.f, v1 = 0.f, v2 = 0.f, v3 = 0.f;
    const int cb = ks * 16 + t4 * 2;
    if (H3) {
        if (n < 12) {
            const float* wp = (n < 4) ? wA : (n < 8 ? wB2 : wC);
            const size_t nb = (size_t)(n & 3) * CIN;
            v0 = wp[(nb + cb) * 9 + tap];
            v1 = wp[(nb + cb + 1) * 9 + tap];
            v2 = wp[(nb + cb + 8) * 9 + tap];
            v3 = wp[(nb + cb + 9) * 9 + tap];
        }
    } else {
        const size_t nb = (size_t)n * CIN;
        v0 = wA[(nb + cb) * 9 + tap];
        v1 = wA[(nb + cb + 1) * 9 + tap];
        v2 = wA[(nb + cb + 8) * 9 + tap];
        v3 = wA[(nb + cb + 9) * 9 + tap];
    }
    uint2 e;
    e.x = pack_h2(v0, v1);
    e.y = pack_h2(v2, v3);
    out[i] = e;
}

__global__ void wprep_k(const float* __restrict__ w2, const float* __restrict__ w3,
                        const float* __restrict__ hA, const float* __restrict__ hB,
                        const float* __restrict__ hC,
                        uint2* __restrict__ o2, uint2* __restrict__ o3, uint2* __restrict__ oH)
{
    constexpr int T2 = 9 * 2 * 64 * 4;
    constexpr int T3 = 9 * 4 * 32 * 4;
    constexpr int TH = 9 * 2 * 16 * 4;
    int i = blockIdx.x * 256 + threadIdx.x;
    if (i < T2) { wprep_one(w2, nullptr, nullptr, 32, 64, 0, o2, i); return; }
    i -= T2;
    if (i < T3) { wprep_one(w3, nullptr, nullptr, 64, 32, 0, o3, i); return; }
    i -= T3;
    if (i < TH) { wprep_one(hA, hB, hC, 32, 16, 1, oH, i); }
}

// ================= fp16 m16n8k16 3x3 conv (weight-carry row-pairing) =================
template<int CIN, int NTOT, int MW, int MT, int NT, bool H3, int GRP>
__global__ __launch_bounds__(256, 2) void mconv_k(
    const __half* __restrict__ in, const uint2* __restrict__ wp,
    const float* __restrict__ bA, const float* __restrict__ bB2, const float* __restrict__ bC,
    const float* __restrict__ pr, void* __restrict__ outv, float* __restrict__ gpart)
{
    constexpr int P = MW * MT * 16;
    constexpr int PP = P + 2;
    constexpr int NKS = CIN / 16;
    constexpr int SEGS = 2 * NKS;
    constexpr int SLOTU2 = NKS * PP * 4;
    constexpr int WSEGS = 9 * NKS * NTOT * 2;

    extern __shared__ __align__(16) char smraw[];
    const uint2* w_u2 = (const uint2*)smraw + 4 * SLOTU2;
    const uint32_t a_u = smem_u32(smraw);
    const uint32_t w_addr = a_u + (uint32_t)(4 * SLOTU2 * 8);

    const int tid = threadIdx.x;
    const int lane = tid & 31;
    const int wid = tid >> 5;
    const int g = lane >> 2, tg = lane & 3;
    const int lrow = lane & 15, lhalf = lane >> 4;
    const int mbase = (wid % MW) * MT * 16;
    const int nbase = (wid / MW) * NT * 8;
    const int x0 = blockIdx.x * P;
    const int y0 = blockIdx.y * 8;
    const int b = blockIdx.z;

    const __half* inb = in + (size_t)b * HW * CIN;

    auto stage = [&](int yy) {
        const int slot = (yy + 4) & 3;
        const uint32_t sbase = a_u + (uint32_t)(slot * SLOTU2 * 8);
        const bool rok = ((unsigned)yy < HH);
        const __half* rowp = inb + (size_t)yy * WW * CIN;
        for (int i = tid; i < PP * SEGS; i += 256) {
            const int p = i / SEGS;
            const int s = i % SEGS;
            const int ks = s >> 1, h = s & 1;
            const int gx = x0 + p - 1;
            const uint32_t dst = sbase + (uint32_t)(ks * PP * 32) + psw(p, h);
            if (rok && (unsigned)gx < WW)
                CP_A16(dst, rowp + (size_t)gx * CIN + ks * 16 + h * 8);
            else
                STZ16(dst);
        }
    };

    for (int i = tid; i < WSEGS; i += 256)
        CP_A16(w_addr + (uint32_t)i * 16, (const char*)wp + (size_t)i * 16);
    if (GRP == 2) { stage(y0 - 1); stage(y0); stage(y0 + 1); stage(y0 + 2); }
    else          { stage(y0 - 1); stage(y0); stage(y0 + 1); }
    CP_COMMIT();

    __half* obH = (__half*)outv + (size_t)b * HW * NTOT;
    const float alpha = pr ? pr[0] : 0.f;
    const int pb0 = mbase + lrow;

    float gs[NT][2];   // GAP partial sums (H3 only)
    #pragma unroll
    for (int nt = 0; nt < NT; nt++) { gs[nt][0] = 0.f; gs[nt][1] = 0.f; }

    auto epi = [&](int y, float (*acc)[NT][4]) {
        #pragma unroll
        for (int mt = 0; mt < MT; mt++) {
            const int px = x0 + mbase + mt * 16 + g;
            #pragma unroll
            for (int nt = 0; nt < NT; nt++) {
                const int ch = nbase + nt * 8 + tg * 2;
                if (H3) {
                    if (ch < 12) {
                        const int st = ch >> 2, c4 = ch & 3;
                        const float* bp = (st == 0) ? bA : (st == 1 ? bB2 : bC);
                        const float bv0 = bp[c4], bv1 = bp[c4 + 1];
                        float* hb = (float*)outv + st * SST + (size_t)b * HW * 4;
                        float2 lo = make_float2(acc[mt][nt][0] + bv0, acc[mt][nt][1] + bv1);
                        float2 hi = make_float2(acc[mt][nt][2] + bv0, acc[mt][nt][3] + bv1);
                        *(float2*)(hb + ((size_t)y * WW + px) * 4 + c4) = lo;
                        *(float2*)(hb + ((size_t)y * WW + px + 8) * 4 + c4) = hi;
                        gs[nt][0] += lo.x + hi.x;
                        gs[nt][1] += lo.y + hi.y;
                    }
                } else {
                    const float bv0 = bA[ch], bv1 = bA[ch + 1];
                    float v0 = acc[mt][nt][0] + bv0;
                    float v1 = acc[mt][nt][1] + bv1;
                    float v2 = acc[mt][nt][2] + bv0;
                    float v3 = acc[mt][nt][3] + bv1;
                    if (v0 < 0.f) v0 *= alpha;
                    if (v1 < 0.f) v1 *= alpha;
                    if (v2 < 0.f) v2 *= alpha;
                    if (v3 < 0.f) v3 *= alpha;
                    *(uint32_t*)(obH + ((size_t)y * WW + px) * NTOT + ch) = pack_h2(v0, v1);
                    *(uint32_t*)(obH + ((size_t)y * WW + px + 8) * NTOT + ch) = pack_h2(v2, v3);
                }
            }
        }
    };

    if (GRP == 2) {
        #pragma unroll 1
        for (int gi = 0; gi < 4; gi++) {
            const int y = y0 + 2 * gi;
            CP_WAIT0();
            __syncthreads();

            float acc[2][MT][NT][4];
            #pragma unroll
            for (int o = 0; o < 2; o++)
                #pragma unroll
                for (int mt = 0; mt < MT; mt++)
                    #pragma unroll
                    for (int nt = 0; nt < NT; nt++)
                        #pragma unroll
                        for (int e = 0; e < 4; e++) acc[o][mt][nt][e] = 0.f;

            // ks-outer, weight-carry ping-pong: each tap weight loaded ONCE per (gi,ks)
            #pragma unroll
            for (int ks = 0; ks < NKS; ks++) {
                uint2 qe[3][NT], qo[3][NT];
                #pragma unroll
                for (int rof = 0; rof < 4; rof++) {
                    const int slot = (y + 3 + rof) & 3;   // input row y-1+rof
                    const uint32_t kbase = a_u + (uint32_t)(((slot * NKS + ks) * PP) * 32);
                    #pragma unroll
                    for (int dx = 0; dx < 3; dx++) {
                        if (rof < 3) {
                            const int tap = rof * 3 + dx;   // dy = rof
                            #pragma unroll
                            for (int nt = 0; nt < NT; nt++) {
                                const uint2 w = w_u2[((tap * NKS + ks) * NTOT + nbase + nt * 8 + g) * 4 + tg];
                                if (rof & 1) qo[dx][nt] = w; else qe[dx][nt] = w;
                            }
                        }
                        uint32_t m[MT][4];
                        #pragma unroll
                        for (int mt = 0; mt < MT; mt++)
                            ldsm4(m[mt], kbase + psw(pb0 + mt * 16 + dx, lhalf));
                        if (rof < 3) {  // o=0, dy=rof -> buffer parity rof
                            #pragma unroll
                            for (int nt = 0; nt < NT; nt++) {
                                const uint2 w = (rof & 1) ? qo[dx][nt] : qe[dx][nt];
                                #pragma unroll
                                for (int mt = 0; mt < MT; mt++)
                                    mma16(acc[0][mt][nt], m[mt][0], m[mt][1], m[mt][2], m[mt][3], w.x, w.y);
                            }
                        }
                        if (rof > 0) {  // o=1, dy=rof-1 -> buffer parity rof-1
                            #pragma unroll
                            for (int nt = 0; nt < NT; nt++) {
                                const uint2 w = ((rof - 1) & 1) ? qo[dx][nt] : qe[dx][nt];
                                #pragma unroll
                                for (int mt = 0; mt < MT; mt++)
                                    mma16(acc[1][mt][nt], m[mt][0], m[mt][1], m[mt][2], m[mt][3], w.x, w.y);
                            }
                        }
                    }
                }
            }

            __syncthreads();
            if (gi < 3) { stage(y + 3); stage(y + 4); CP_COMMIT(); }
            epi(y, acc[0]);
            epi(y + 1, acc[1]);
        }
    } else {
        #pragma unroll 1
        for (int yi = 0; yi < 8; yi++) {
            const int y = y0 + yi;
            CP_WAIT0();
            __syncthreads();
            if (yi < 7) { stage(y + 2); CP_COMMIT(); }

            float acc[MT][NT][4];
            #pragma unroll
            for (int mt = 0; mt < MT; mt++)
                #pragma unroll
                for (int nt = 0; nt < NT; nt++)
                    #pragma unroll
                    for (int e = 0; e < 4; e++) acc[mt][nt][e] = 0.f;

            #pragma unroll 1
            for (int tap = 0; tap < 9; tap++) {
                const int dy = tap / 3, dx = tap - dy * 3;
                const int slot = (y + dy + 3) & 3;
                #pragma unroll
                for (int ks = 0; ks < NKS; ks++) {
                    const uint32_t kbase = a_u + (uint32_t)(((slot * NKS + ks) * PP) * 32);
                    uint32_t m[MT][4];
                    #pragma unroll
                    for (int mt = 0; mt < MT; mt++)
                        ldsm4(m[mt], kbase + psw(pb0 + mt * 16 + dx, lhalf));
                    #pragma unroll
                    for (int nt = 0; nt < NT; nt++) {
                        const uint2 qw = w_u2[((tap * NKS + ks) * NTOT + nbase + nt * 8 + g) * 4 + tg];
                        #pragma unroll
                        for (int mt = 0; mt < MT; mt++)
                            mma16(acc[mt][nt], m[mt][0], m[mt][1], m[mt][2], m[mt][3], qw.x, qw.y);
                    }
                }
            }
            epi(y, acc);
        }
    }

    // ---- fused GAP partial reduction (H3 only; MW=8 so nbase==0 for all warps) ----
    if (H3) {
        #pragma unroll
        for (int nt = 0; nt < NT; nt++)
            #pragma unroll
            for (int e = 0; e < 2; e++) {
                float v = gs[nt][e];
                v += __shfl_xor_sync(0xffffffffu, v, 4);
                v += __shfl_xor_sync(0xffffffffu, v, 8);
                v += __shfl_xor_sync(0xffffffffu, v, 16);
                gs[nt][e] = v;
            }
        __syncthreads();
        float* sred = (float*)smraw;   // [wid][tg][4]
        if (g == 0) {
            #pragma unroll
            for (int nt = 0; nt < NT; nt++) {
                sred[(wid * 4 + tg) * 4 + nt * 2 + 0] = gs[nt][0];
                sred[(wid * 4 + tg) * 4 + nt * 2 + 1] = gs[nt][1];
            }
        }
        __syncthreads();
        if (tid < 12) {
            const int c = tid;
            const int nt = c >> 3, tgc = (c & 7) >> 1, e = c & 1;
            float s = 0.f;
            #pragma unroll
            for (int w = 0; w < 8; w++) s += sred[(w * 4 + tgc) * 4 + nt * 2 + e];
            const int pbid = blockIdx.x * 64 + blockIdx.y;
            gpart[((size_t)b * 128 + pbid) * 12 + c] = s;
        }
    }
}

// ================= conv1: 3->32, f32x2 FMA + LDS.128 weights =================
__global__ __launch_bounds__(256) void conv1_k(
    const float* __restrict__ x, const float* __restrict__ w,
    const float* __restrict__ bias, const float* __restrict__ pr,
    __half* __restrict__ out)
{
    __shared__ float s_in[3][10][34];
    __shared__ ulonglong2 s_w4[27][8];
    __shared__ float s_b[32];

    const int tid = threadIdx.x;
    const int tx = tid & 31, ty = tid >> 5;
    const int x0 = blockIdx.x * 32, y0 = blockIdx.y * 8;
    const int b = blockIdx.z;

    for (int i = tid; i < 216; i += 256) {
        const int t = i / 8, j = i % 8;
        const uint32_t a0 = __float_as_uint(w[(4 * j) * 27 + t]);
        const uint32_t a1 = __float_as_uint(w[(4 * j + 1) * 27 + t]);
        const uint32_t a2 = __float_as_uint(w[(4 * j + 2) * 27 + t]);
        const uint32_t a3 = __float_as_uint(w[(4 * j + 3) * 27 + t]);
        ulonglong2 e;
        e.x = ((unsigned long long)a1 << 32) | a0;
        e.y = ((unsigned long long)a3 << 32) | a2;
        s_w4[t][j] = e;
    }
    if (tid < 32) s_b[tid] = bias[tid];
    for (int i = tid; i < 1020; i += 256) {
        const int c = i / 340, r = i % 340;
        const int rr = r / 34, cc = r % 34;
        const int gy = y0 - 1 + rr, gx = x0 - 1 + cc;
        float v = 0.f;
        if ((unsigned)gy < HH && (unsigned)gx < WW)
            v = x[((size_t)(b * 3 + c)) * HW + (size_t)gy * WW + gx];
        s_in[c][rr][cc] = v;
    }
    __syncthreads();

    float vin[27];
    #pragma unroll
    for (int c = 0; c < 3; c++)
        #pragma unroll
        for (int dy = 0; dy < 3; dy++)
            #pragma unroll
            for (int dx = 0; dx < 3; dx++)
                vin[c * 9 + dy * 3 + dx] = s_in[c][ty + dy][tx + dx];

    unsigned long long acc2[16];
    #pragma unroll
    for (int j = 0; j < 16; j++) acc2[j] = 0ull;
    #pragma unroll
    for (int t = 0; t < 27; t++) {
        unsigned long long vv;
        asm("mov.b64 %0, {%1, %1};" : "=l"(vv) : "r"(__float_as_uint(vin[t])));
        #pragma unroll
        for (int j = 0; j < 8; j++) {
            const ulonglong2 ww = s_w4[t][j];
            fma2(acc2[2 * j], vv, ww.x);
            fma2(acc2[2 * j + 1], vv, ww.y);
        }
    }

    const float alpha = pr[0];
    uint32_t uu[16];
    #pragma unroll
    for (int j = 0; j < 16; j++) {
        uint32_t lo, hi;
        asm("mov.b64 {%0, %1}, %2;" : "=r"(lo), "=r"(hi) : "l"(acc2[j]));
        float v0 = __uint_as_float(lo) + s_b[2 * j];
        float v1 = __uint_as_float(hi) + s_b[2 * j + 1];
        if (v0 < 0.f) v0 *= alpha;
        if (v1 < 0.f) v1 *= alpha;
        uu[j] = pack_h2(v0, v1);
    }
    __half* dst = out + ((size_t)b * HW + (size_t)(y0 + ty) * WW + x0 + tx) * 32;
    #pragma unroll
    for (int q = 0; q < 4; q++)
        ((uint4*)dst)[q] = make_uint4(uu[4 * q], uu[4 * q + 1], uu[4 * q + 2], uu[4 * q + 3]);
}

// ================= fused GAP-combine + SE (reads per-block partials) =================
__global__ void gapse_k(const float* __restrict__ part,
                        const float* __restrict__ c1a, const float* __restrict__ c2a,
                        const float* __restrict__ c1b, const float* __restrict__ c2b,
                        const float* __restrict__ c1c, const float* __restrict__ c2c,
                        float* __restrict__ sout)
{
    __shared__ float gg[8][12];
    __shared__ float tt[8][12];
    const int t = threadIdx.x;
    const int b = t / 12, c = t % 12;
    const int st = c >> 2, c4 = c & 3;
    const float* c1 = (st == 0) ? c1a : (st == 1 ? c1b : c1c);
    const float* c2 = (st == 0) ? c2a : (st == 1 ? c2b : c2c);
    if (t < 96) {
        float s = 0.f;
        for (int k = 0; k < 128; k++) s += part[((size_t)b * 128 + k) * 12 + c];
        gg[b][c] = s * (1.0f / HW);
    }
    __syncthreads();
    if (t < 96) {
        float v = 0.f;
        #pragma unroll
        for (int k = 0; k < 4; k++) v += c1[c4 * 4 + k] * gg[b][st * 4 + k];
        tt[b][c] = fmaxf(v, 0.f);
    }
    __syncthreads();
    if (t < 96) {
        float v = 0.f;
        #pragma unroll
        for (int k = 0; k < 4; k++) v += c2[c4 * 4 + k] * tt[b][st * 4 + k];
        sout[st * 32 + b * 4 + c4] = 1.f / (1.f + __expf(-v));
    }
}

// ================= fused blur + softmax + combine, 64x64 tiles =================
__global__ __launch_bounds__(256) void blurfuse_k(
    const float* __restrict__ src, const float* __restrict__ hp,
    const float* __restrict__ sv, float* __restrict__ out)
{
    extern __shared__ float bsm[];
    float (*s_src)[89] = (float(*)[89])bsm;
    float (*s_h5)[84]  = (float(*)[84])(bsm + 88 * 89);
    float (*s_h15)[64] = (float(*)[64])(bsm + 88 * 89 + 88 * 84);
    float (*s_h25)[64] = (float(*)[64])(bsm + 88 * 89 + 88 * 84 + 88 * 64);

    const int tx = threadIdx.x, ty = threadIdx.y;
    const int tid = ty * 64 + tx;
    const int x0 = blockIdx.x * 64, y0 = blockIdx.y * 64;
    const int z = blockIdx.z;
    const int c = z % 3, b = z / 3;
    const size_t cb = (size_t)(b * 3 + c) * HW;

    for (int i = tid; i < 88 * 88; i += 256) {
        const int r = i / 88, cc = i % 88;
        const int gy = y0 - 12 + r, gx = x0 - 12 + cc;
        float v = 0.f;
        if ((unsigned)gy < HH && (unsigned)gx < WW)
            v = src[cb + (size_t)gy * WW + gx];
        s_src[r][cc] = v;
    }
    __syncthreads();

    for (int i = tid; i < 88 * 84; i += 256) {
        const int r = i / 84, j = i % 84;
        s_h5[r][j] = s_src[r][j] + s_src[r][j + 1] + s_src[r][j + 2]
                   + s_src[r][j + 3] + s_src[r][j + 4];
    }
    __syncthreads();

    for (int i = tid; i < 88 * 64; i += 256) {
        const int r = i / 64, t = i % 64;
        const float h15 = s_h5[r][t + 5] + s_h5[r][t + 10] + s_h5[r][t + 15];
        s_h15[r][t] = h15;
        s_h25[r][t] = h15 + s_h5[r][t] + s_h5[r][t + 20];
    }
    __syncthreads();

    const int r0 = ty * 16 + 12;
    float v5 = 0.f, v15 = 0.f, v25 = 0.f;
    #pragma unroll
    for (int d = -2; d <= 2; d++) v5 += s_h5[r0 + d][tx + 10];
    #pragma unroll
    for (int d = -7; d <= 7; d++) v15 += s_h15[r0 + d][tx];
    #pragma unroll
    for (int d = -12; d <= 12; d++) v25 += s_h25[r0 + d][tx];

    const float s0 = sv[b * 4 + 0], s1 = sv[b * 4 + 1], s2 = sv[b * 4 + 2], s3 = sv[b * 4 + 3];
    const int x = x0 + tx;
    const float4* hppix = (const float4*)(hp + (size_t)b * HW * 4);

    #pragma unroll 1
    for (int j = 0; j < 16; j++) {
        const int y = y0 + ty * 16 + j;
        const int r = r0 + j;
        const float4 hv = hppix[(size_t)y * WW + x];
        float e0 = hv.x * s0, e1 = hv.y * s1, e2 = hv.z * s2, e3 = hv.w * s3;
        float m = fmaxf(fmaxf(e0, e1), fmaxf(e2, e3));
        float w0 = __expf(e0 - m), w1 = __expf(e1 - m), w2 = __expf(e2 - m), w3 = __expf(e3 - m);
        float inv = 1.f / (w0 + w1 + w2 + w3);
        float o = (w0 * inv) * s_src[r][tx + 12]
                + (w1 * inv) * (v5 * (1.f / 25.f))
                + (w2 * inv) * (v15 * (1.f / 225.f))
                + (w3 * inv) * (v25 * (1.f / 625.f));
        out[cb + (size_t)y * WW + x] = o;
        if (j < 15) {
            v5 += s_h5[r + 3][tx + 10] - s_h5[r - 2][tx + 10];
            v15 += s_h15[r + 8][tx] - s_h15[r - 7][tx];
            v25 += s_h25[r + 13][tx] - s_h25[r - 12][tx];
        }
    }
}

// ================= launch =================
extern "C" void kernel_launch(void* const* d_in, const int* in_sizes, int n_in,
                              void* d_out, int out_size)
{
    const float* x   = (const float*)d_in[0];
    const float* bw1 = (const float*)d_in[1];
    const float* bb1 = (const float*)d_in[2];
    const float* a1  = (const float*)d_in[3];
    const float* bw2 = (const float*)d_in[4];
    const float* bb2 = (const float*)d_in[5];
    const float* a2  = (const float*)d_in[6];
    const float* bw3 = (const float*)d_in[7];
    const float* bb3 = (const float*)d_in[8];
    const float* a3  = (const float*)d_in[9];
    const float* hw_[3]  = { (const float*)d_in[10], (const float*)d_in[14], (const float*)d_in[18] };
    const float* hb_[3]  = { (const float*)d_in[11], (const float*)d_in[15], (const float*)d_in[19] };
    const float* hc1_[3] = { (const float*)d_in[12], (const float*)d_in[16], (const float*)d_in[20] };
    const float* hc2_[3] = { (const float*)d_in[13], (const float*)d_in[17], (const float*)d_in[21] };

    float *B1, *B2, *P, *S, *TX, *TX2;
    uint2 *W2p, *W3p, *WHp;
    cudaGetSymbolAddress((void**)&B1, g_B1);
    cudaGetSymbolAddress((void**)&B2, g_B2);
    cudaGetSymbolAddress((void**)&P, g_P);
    cudaGetSymbolAddress((void**)&S, g_S);
    cudaGetSymbolAddress((void**)&TX, g_TX);
    cudaGetSymbolAddress((void**)&TX2, g_TX2);
    cudaGetSymbolAddress((void**)&W2p, g_W2);
    cudaGetSymbolAddress((void**)&W3p, g_W3);
    cudaGetSymbolAddress((void**)&WHp, g_WH);
    __half* B1h = (__half*)B1;
    __half* B2h = (__half*)B2;

    const int smem2 = 4 * 2 * 258 * 32 + 9 * 2 * 64 * 32;  // 102912
    const int smem3 = 4 * 4 * 130 * 32 + 9 * 4 * 32 * 32;  // 103424
    const int smemH = 4 * 2 * 258 * 32 + 9 * 2 * 16 * 32;  // 75264
    const int smemF = (88 * 89 + 88 * 84 + 2 * 88 * 64) * 4;  // 105952
    cudaFuncSetAttribute((const void*)mconv_k<32, 64, 4, 4, 4, false, 1>,
                         cudaFuncAttributeMaxDynamicSharedMemorySize, smem2);
    cudaFuncSetAttribute((const void*)mconv_k<64, 32, 4, 2, 2, false, 2>,
                         cudaFuncAttributeMaxDynamicSharedMemorySize, smem3);
    cudaFuncSetAttribute((const void*)mconv_k<32, 16, 8, 2, 2, true, 2>,
                         cudaFuncAttributeMaxDynamicSharedMemorySize, smemH);
    cudaFuncSetAttribute((const void*)blurfuse_k,
                         cudaFuncAttributeMaxDynamicSharedMemorySize, smemF);

    // ---- weight pre-transform ----
    wprep_k<<<(4608 + 4608 + 1152 + 255) / 256, 256>>>(bw2, bw3, hw_[0], hw_[1], hw_[2],
                                                       W2p, W3p, WHp);

    // ---- body ----
    conv1_k<<<dim3(16, 64, BB), 256>>>(x, bw1, bb1, a1, B1h);
    mconv_k<32, 64, 4, 4, 4, false, 1><<<dim3(2, 64, BB), 256, smem2>>>(
        B1h, W2p, bb2, nullptr, nullptr, a2, B2h, nullptr);
    mconv_k<64, 32, 4, 2, 2, false, 2><<<dim3(4, 64, BB), 256, smem3>>>(
        B2h, W3p, bb3, nullptr, nullptr, a3, B1h, nullptr);

    // ---- heads -> 3 packed stage buffers + fused GAP partials ----
    float* HP = B2;
    mconv_k<32, 16, 8, 2, 2, true, 2><<<dim3(2, 64, BB), 256, smemH>>>(
        B1h, WHp, hb_[0], hb_[1], hb_[2], nullptr, HP, P);
    gapse_k<<<1, 96>>>(P, hc1_[0], hc2_[0], hc1_[1], hc2_[1], hc1_[2], hc2_[2], S);

    // ---- fused blur+softmax+combine (ping-pong) ----
    const dim3 fgrid(8, 8, BB * 3);
    const dim3 fblk(64, 4);
    blurfuse_k<<<fgrid, fblk, smemF>>>(x,   HP + 0 * SST, S + 0,  TX);
    blurfuse_k<<<fgrid, fblk, smemF>>>(TX,  HP + 1 * SST, S + 32, TX2);
    blurfuse_k<<<fgrid, fblk, smemF>>>(TX2, HP + 2 * SST, S + 64, (float*)d_out);
    (void)in_sizes; (void)n_in; (void)out_size;
}